// round 4
// baseline (speedup 1.0000x reference)
#include <cuda_runtime.h>
#include <cuda_fp16.h>
#include <cstdint>

// Problem constants
#define TOKENS 32768          // B*S = 16*2048
#define FDIM   1024
#define NQKV   3072
#define NHEAD  16
#define DHEAD  64

// ---------------------------------------------------------------------------
// Scratch (device globals; no allocations allowed)
// ---------------------------------------------------------------------------
__device__ __align__(16) half  g_X16 [(size_t)TOKENS * FDIM];   // x in fp16
__device__ __align__(16) half  g_Wqkv[(size_t)NQKV * FDIM];     // [N=3072, K=1024] transposed
__device__ __align__(16) half  g_Wo16[(size_t)FDIM * FDIM];     // [N=1024, K=1024] transposed
__device__ float               g_bqkv[NQKV];                    // packed biases
__device__ __align__(16) half  g_QKV [(size_t)TOKENS * NQKV];   // q,k,v per token
__device__ __align__(16) half  g_Attn[(size_t)TOKENS * FDIM];   // attention output

// ---------------------------------------------------------------------------
// PTX helpers
// ---------------------------------------------------------------------------
__device__ __forceinline__ void cp_async16(void* dst, const void* src){
    unsigned s = (unsigned)__cvta_generic_to_shared(dst);
    asm volatile("cp.async.cg.shared.global [%0], [%1], 16;\n" :: "r"(s), "l"(src));
}
__device__ __forceinline__ void cp_commit(){ asm volatile("cp.async.commit_group;\n"); }
template<int N>
__device__ __forceinline__ void cp_wait(){ asm volatile("cp.async.wait_group %0;\n" :: "n"(N)); }

__device__ __forceinline__ void ldsm_x4(uint32_t* r, uint32_t addr){
    asm volatile("ldmatrix.sync.aligned.m8n8.x4.shared.b16 {%0,%1,%2,%3}, [%4];\n"
        : "=r"(r[0]), "=r"(r[1]), "=r"(r[2]), "=r"(r[3]) : "r"(addr));
}
__device__ __forceinline__ void mma16816(float* c, const uint32_t* a, const uint32_t* b){
    asm volatile("mma.sync.aligned.m16n8k16.row.col.f32.f16.f16.f32 "
        "{%0,%1,%2,%3}, {%4,%5,%6,%7}, {%8,%9}, {%0,%1,%2,%3};\n"
        : "+f"(c[0]), "+f"(c[1]), "+f"(c[2]), "+f"(c[3])
        : "r"(a[0]), "r"(a[1]), "r"(a[2]), "r"(a[3]), "r"(b[0]), "r"(b[1]));
}

// ---------------------------------------------------------------------------
// Convert x fp32 -> fp16, and pack biases
// ---------------------------------------------------------------------------
__global__ void __launch_bounds__(256) convx_kernel(const float* __restrict__ x,
    const float* __restrict__ bq, const float* __restrict__ bk, const float* __restrict__ bv)
{
    const size_t n4 = (size_t)TOKENS * FDIM / 4;
    size_t gid = (size_t)blockIdx.x * blockDim.x + threadIdx.x;
    size_t stride = (size_t)gridDim.x * blockDim.x;
    for (size_t i = gid; i < n4; i += stride){
        float4 v = ((const float4*)x)[i];
        ((half2*)g_X16)[2*i]   = __floats2half2_rn(v.x, v.y);
        ((half2*)g_X16)[2*i+1] = __floats2half2_rn(v.z, v.w);
    }
    if (gid < NQKV){
        g_bqkv[gid] = (gid < 1024) ? bq[gid] : (gid < 2048) ? bk[gid - 1024] : bv[gid - 2048];
    }
}

// ---------------------------------------------------------------------------
// Tiled transpose: W[k][n] fp32 -> Wt[n][k] fp16.  z: 0..2 -> Wqkv rows, 3 -> Wo
// ---------------------------------------------------------------------------
__global__ void __launch_bounds__(256) transw_kernel(
    const float* __restrict__ Wq, const float* __restrict__ Wk,
    const float* __restrict__ Wv, const float* __restrict__ Wo)
{
    __shared__ float t[32][33];
    const int z = blockIdx.z;
    const float* src = (z == 0) ? Wq : (z == 1) ? Wk : (z == 2) ? Wv : Wo;
    const int k0 = blockIdx.y * 32, n0 = blockIdx.x * 32;
    const int tx = threadIdx.x, ty = threadIdx.y;   // 32 x 8
    #pragma unroll
    for (int i = 0; i < 4; ++i)
        t[ty + i * 8][tx] = src[(size_t)(k0 + ty + i * 8) * FDIM + n0 + tx];
    __syncthreads();
    half* dst = (z < 3) ? (g_Wqkv + (size_t)z * FDIM * FDIM) : g_Wo16;
    #pragma unroll
    for (int i = 0; i < 4; ++i)
        dst[(size_t)(n0 + ty + i * 8) * FDIM + k0 + tx] = __float2half_rn(t[tx][ty + i * 8]);
}

// ---------------------------------------------------------------------------
// GEMM1 (HMMA): QKV[M,3072] = X[M,1024] * Wqkv[3072,1024]^T + bqkv
//   CTA 128x256, 8 warps (2x4), warp 64x64, BK=64, 4-stage cp.async ring.
// ---------------------------------------------------------------------------
#define BM 128
#define BN 256
#define BK 64
#define SROW 72
#define A_ST_BYTES (BM * SROW * 2)
#define B_ST_BYTES (BN * SROW * 2)
#define STAGE_BYTES (A_ST_BYTES + B_ST_BYTES)
#define NSTAGES 4
#define NKBLK (FDIM / BK)
#define GEMM_DSMEM (NSTAGES * STAGE_BYTES)

__global__ void __launch_bounds__(256, 1) gemm1_kernel()
{
    extern __shared__ __align__(16) half sm[];

    const int tid  = threadIdx.x;
    const int lane = tid & 31;
    const int wid  = tid >> 5;
    const int wm   = wid & 1;
    const int wn   = wid >> 1;
    const int m0 = blockIdx.y * BM;
    const int n0 = blockIdx.x * BN;

    const half* Abase = g_X16  + (size_t)m0 * FDIM;
    const half* Bbase = g_Wqkv + (size_t)n0 * FDIM;

    float acc[4][8][4];
    #pragma unroll
    for (int mi = 0; mi < 4; ++mi)
        #pragma unroll
        for (int ni = 0; ni < 8; ++ni)
            #pragma unroll
            for (int t = 0; t < 4; ++t) acc[mi][ni][t] = 0.f;

    auto load_stage = [&](int s){
        const int buf = s & (NSTAGES - 1);
        half* as = sm + (size_t)buf * (STAGE_BYTES / 2);
        half* bs = as + (A_ST_BYTES / 2);
        const half* Asrc = Abase + s * BK;
        const half* Bsrc = Bbase + s * BK;
        #pragma unroll
        for (int i = 0; i < 4; ++i){
            int idx = tid + i * 256;
            int r = idx >> 3, c = idx & 7;
            cp_async16(as + r * SROW + c * 8, Asrc + (size_t)r * FDIM + c * 8);
        }
        #pragma unroll
        for (int i = 0; i < 8; ++i){
            int idx = tid + i * 256;
            int r = idx >> 3, c = idx & 7;
            cp_async16(bs + r * SROW + c * 8, Bsrc + (size_t)r * FDIM + c * 8);
        }
        cp_commit();
    };

    load_stage(0); load_stage(1); load_stage(2);

    const int a_row = wm * 64 + (lane & 15);
    const int a_colb = (lane >> 4) << 3;
    const int b_row = wn * 64 + (lane & 7) + ((lane >> 4) << 3);
    const int b_colb = ((lane >> 3) & 1) << 3;

    for (int s = 0; s < NKBLK; ++s){
        const int rem = (NKBLK - 1) - s;
        if (rem >= 2)      cp_wait<2>();
        else if (rem == 1) cp_wait<1>();
        else               cp_wait<0>();
        __syncthreads();

        if (s + 3 < NKBLK) load_stage(s + 3);

        const int buf = s & (NSTAGES - 1);
        const half* as = sm + (size_t)buf * (STAGE_BYTES / 2);
        const half* bs = as + (A_ST_BYTES / 2);
        const uint32_t aB = (uint32_t)__cvta_generic_to_shared(as);
        const uint32_t bB = (uint32_t)__cvta_generic_to_shared(bs);

        #pragma unroll
        for (int kk = 0; kk < 4; ++kk){
            const int k16 = kk * 16;
            uint32_t a[4][4], b[8][2];
            #pragma unroll
            for (int mi = 0; mi < 4; ++mi){
                uint32_t addr = aB + (uint32_t)(((a_row + mi * 16) * SROW + k16 + a_colb) * 2);
                ldsm_x4(&a[mi][0], addr);
            }
            #pragma unroll
            for (int nb = 0; nb < 4; ++nb){
                uint32_t addr = bB + (uint32_t)(((b_row + nb * 16) * SROW + k16 + b_colb) * 2);
                uint32_t r[4];
                ldsm_x4(r, addr);
                b[nb * 2][0] = r[0];     b[nb * 2][1] = r[1];
                b[nb * 2 + 1][0] = r[2]; b[nb * 2 + 1][1] = r[3];
            }
            #pragma unroll
            for (int mi = 0; mi < 4; ++mi)
                #pragma unroll
                for (int ni = 0; ni < 8; ++ni)
                    mma16816(acc[mi][ni], a[mi], b[ni]);
        }
    }

    #pragma unroll
    for (int mi = 0; mi < 4; ++mi){
        #pragma unroll
        for (int ni = 0; ni < 8; ++ni){
            int r = m0 + wm * 64 + mi * 16 + (lane >> 2);
            int c = n0 + wn * 64 + ni * 8 + ((lane & 3) << 1);
            float b0 = g_bqkv[c], b1 = g_bqkv[c + 1];
            float v0 = acc[mi][ni][0] + b0, v1 = acc[mi][ni][1] + b1;
            float v2 = acc[mi][ni][2] + b0, v3 = acc[mi][ni][3] + b1;
            *(half2*)(g_QKV + (size_t)r * NQKV + c)       = __floats2half2_rn(v0, v1);
            *(half2*)(g_QKV + (size_t)(r + 8) * NQKV + c) = __floats2half2_rn(v2, v3);
        }
    }
}

// ---------------------------------------------------------------------------
// Per-token cross-head attention. 1 warp per token, 8 tokens per block.
// SMEM per token (half2 units): q[16][32] at 0, k[16][34] at 512, v[16][34]
// at 1056 -> 1600 half2 per token. 34-stride makes k/v bank = (2g+d)&31,
// distinct across all 32 lanes (16 h x 2 gb) -> conflict-free.
// ---------------------------------------------------------------------------
#define ATTN_TOK_H2 1600
#define ATTN_DSMEM (8 * ATTN_TOK_H2 * 4)   // 51200 bytes

__global__ void __launch_bounds__(256) attn_kernel(){
    extern __shared__ __align__(16) half2 sq[];
    const int tid = threadIdx.x, lane = tid & 31, w = tid >> 5;
    const size_t tok0 = (size_t)blockIdx.x * 8;

    // scatter-load 8 tokens x 1536 half2 into padded layout
    int off[6];
    #pragma unroll
    for (int c2 = 0; c2 < 6; ++c2){
        int j = tid + c2 * 256;
        int o;
        if (j < 512) o = j;
        else if (j < 1024){ int e = j - 512;  o = 512  + (e >> 5) * 34 + (e & 31); }
        else              { int e = j - 1024; o = 1056 + (e >> 5) * 34 + (e & 31); }
        off[c2] = o;
    }
    const half2* src = (const half2*)(g_QKV + tok0 * NQKV);
    #pragma unroll
    for (int t = 0; t < 8; ++t){
        const half2* s = src + (size_t)t * 1536;
        half2* dst = sq + t * ATTN_TOK_H2;
        #pragma unroll
        for (int c2 = 0; c2 < 6; ++c2)
            dst[off[c2]] = s[tid + c2 * 256];
    }
    __syncthreads();

    half2* base = sq + w * ATTN_TOK_H2;
    const half2* q2 = base;
    const half2* k2 = base + 512;
    const half2* v2 = base + 1056;
    const int h  = lane >> 1;
    const int gb = (lane & 1) << 3;

    // q row into registers (rotated by h; pair lanes broadcast -> conflict-free)
    float2 qr[32];
    #pragma unroll
    for (int j = 0; j < 32; ++j){
        int d = (j + h) & 31;
        qr[j] = __half22float2(q2[h * 32 + d]);
    }

    // energies over this lane's 8 g's
    float e[8];
    #pragma unroll
    for (int gi = 0; gi < 8; ++gi){
        int g = gb + gi;
        float a = 0.f;
        #pragma unroll
        for (int j = 0; j < 32; ++j){
            int d = (j + h) & 31;
            float2 kf = __half22float2(k2[g * 34 + d]);
            a += qr[j].x * kf.x + qr[j].y * kf.y;
        }
        e[gi] = a * 0.125f;
    }

    // softmax over 16 g's split across the lane pair
    float m = e[0];
    #pragma unroll
    for (int gi = 1; gi < 8; ++gi) m = fmaxf(m, e[gi]);
    m = fmaxf(m, __shfl_xor_sync(0xffffffffu, m, 1));
    float ssum = 0.f;
    #pragma unroll
    for (int gi = 0; gi < 8; ++gi){ e[gi] = __expf(e[gi] - m); ssum += e[gi]; }
    ssum += __shfl_xor_sync(0xffffffffu, ssum, 1);
    float inv = 1.f / ssum;

    // out partials over own 8 g's, all 64 d
    float2 o[32];
    #pragma unroll
    for (int j = 0; j < 32; ++j) o[j] = make_float2(0.f, 0.f);
    #pragma unroll
    for (int gi = 0; gi < 8; ++gi){
        float p = e[gi] * inv;
        int g = gb + gi;
        #pragma unroll
        for (int j = 0; j < 32; ++j){
            int d = (j + h) & 31;
            float2 vf = __half22float2(v2[g * 34 + d]);
            o[j].x += p * vf.x; o[j].y += p * vf.y;
        }
    }
    #pragma unroll
    for (int j = 0; j < 32; ++j){
        o[j].x += __shfl_xor_sync(0xffffffffu, o[j].x, 1);
        o[j].y += __shfl_xor_sync(0xffffffffu, o[j].y, 1);
    }
    __syncwarp();

    // even lanes stash into (dead) q region, conflict-free (16 distinct banks)
    half2* outs = base;
    if ((lane & 1) == 0){
        #pragma unroll
        for (int j = 0; j < 32; ++j){
            int d = (j + h) & 31;
            outs[h * 32 + d] = __floats2half2_rn(o[j].x, o[j].y);
        }
    }
    __syncthreads();

    // coalesced store: 8 tokens x 1024 halfs
    float4* gout = (float4*)(g_Attn + tok0 * FDIM);
    #pragma unroll
    for (int i = 0; i < 4; ++i){
        int c = tid + i * 256;
        int tw = c >> 7, off4 = c & 127;
        const float4* p = (const float4*)(sq + tw * ATTN_TOK_H2);
        gout[c] = p[off4];
    }
}

// ---------------------------------------------------------------------------
// GEMM2 + bias + LayerNorm fused: out[M,1024] = LN(Attn @ Wo^T + bo)
//   CTA 32x1024 (full rows!), 8 warps, warp 32x128, BK=32 double buffer.
// ---------------------------------------------------------------------------
#define G2_BM 32
#define G2_BK 32
#define G2_SROW 40
#define G2_A_H (G2_BM * G2_SROW)          // 1280 halfs
#define G2_B_H (FDIM * G2_SROW)           // 40960 halfs
#define G2_STAGE_H (G2_A_H + G2_B_H)      // 42240 halfs
#define G2_DSMEM (2 * G2_STAGE_H * 2)     // 168960 bytes
#define G2_NK (FDIM / G2_BK)              // 32

__global__ void __launch_bounds__(256, 1) gemm2_ln_kernel(
    const float* __restrict__ bo, const float* __restrict__ gamma,
    const float* __restrict__ beta, float* __restrict__ out)
{
    extern __shared__ __align__(16) half sm2[];
    __shared__ float sred[32][8], qred[32][8], smv[32][2];

    const int tid  = threadIdx.x;
    const int lane = tid & 31;
    const int wid  = tid >> 5;         // 0..7 -> 128-col slice
    const int m0 = blockIdx.x * G2_BM;

    const half* Abase = g_Attn + (size_t)m0 * FDIM;

    float acc[2][16][4];
    #pragma unroll
    for (int mi = 0; mi < 2; ++mi)
        #pragma unroll
        for (int ni = 0; ni < 16; ++ni)
            #pragma unroll
            for (int t = 0; t < 4; ++t) acc[mi][ni][t] = 0.f;

    auto load_stage = [&](int s){
        const int buf = s & 1;
        half* as = sm2 + (size_t)buf * G2_STAGE_H;
        half* bs = as + G2_A_H;
        const half* Asrc = Abase  + s * G2_BK;
        const half* Bsrc = g_Wo16 + s * G2_BK;
        if (tid < 128){
            int r = tid >> 2, c = tid & 3;
            cp_async16(as + r * G2_SROW + c * 8, Asrc + (size_t)r * FDIM + c * 8);
        }
        #pragma unroll
        for (int i = 0; i < 16; ++i){
            int idx = tid + i * 256;
            int n = idx >> 2, c = idx & 3;
            cp_async16(bs + n * G2_SROW + c * 8, Bsrc + (size_t)n * FDIM + c * 8);
        }
        cp_commit();
    };

    load_stage(0);

    const int a_row  = lane & 15;
    const int a_colb = (lane >> 4) << 3;
    const int b_row  = wid * 128 + (lane & 7) + ((lane >> 4) << 3);
    const int b_colb = ((lane >> 3) & 1) << 3;

    for (int s = 0; s < G2_NK; ++s){
        cp_wait<0>();
        __syncthreads();
        if (s + 1 < G2_NK) load_stage(s + 1);

        const int buf = s & 1;
        const half* as = sm2 + (size_t)buf * G2_STAGE_H;
        const half* bs = as + G2_A_H;
        const uint32_t aB = (uint32_t)__cvta_generic_to_shared(as);
        const uint32_t bB = (uint32_t)__cvta_generic_to_shared(bs);

        #pragma unroll
        for (int kk = 0; kk < 2; ++kk){
            const int k16 = kk * 16;
            uint32_t a[2][4], b[16][2];
            #pragma unroll
            for (int mi = 0; mi < 2; ++mi){
                uint32_t addr = aB + (uint32_t)(((a_row + mi * 16) * G2_SROW + k16 + a_colb) * 2);
                ldsm_x4(&a[mi][0], addr);
            }
            #pragma unroll
            for (int nb = 0; nb < 8; ++nb){
                uint32_t addr = bB + (uint32_t)(((b_row + nb * 16) * G2_SROW + k16 + b_colb) * 2);
                uint32_t r[4];
                ldsm_x4(r, addr);
                b[nb * 2][0] = r[0];     b[nb * 2][1] = r[1];
                b[nb * 2 + 1][0] = r[2]; b[nb * 2 + 1][1] = r[3];
            }
            #pragma unroll
            for (int mi = 0; mi < 2; ++mi)
                #pragma unroll
                for (int ni = 0; ni < 16; ++ni)
                    mma16816(acc[mi][ni], a[mi], b[ni]);
        }
    }

    // add bias, accumulate per-row partial sum / sumsq (4 rows per thread)
    float ps[4] = {0.f, 0.f, 0.f, 0.f};
    float pq[4] = {0.f, 0.f, 0.f, 0.f};
    #pragma unroll
    for (int mi = 0; mi < 2; ++mi){
        #pragma unroll
        for (int ni = 0; ni < 16; ++ni){
            int c = wid * 128 + ni * 8 + ((lane & 3) << 1);
            float b0 = bo[c], b1 = bo[c + 1];
            float v0 = acc[mi][ni][0] + b0, v1 = acc[mi][ni][1] + b1;
            float v2 = acc[mi][ni][2] + b0, v3 = acc[mi][ni][3] + b1;
            acc[mi][ni][0] = v0; acc[mi][ni][1] = v1;
            acc[mi][ni][2] = v2; acc[mi][ni][3] = v3;
            ps[mi*2]   += v0 + v1;            pq[mi*2]   += v0*v0 + v1*v1;
            ps[mi*2+1] += v2 + v3;            pq[mi*2+1] += v2*v2 + v3*v3;
        }
    }
    #pragma unroll
    for (int t = 0; t < 4; ++t){
        ps[t] += __shfl_xor_sync(0xffffffffu, ps[t], 1);
        ps[t] += __shfl_xor_sync(0xffffffffu, ps[t], 2);
        pq[t] += __shfl_xor_sync(0xffffffffu, pq[t], 1);
        pq[t] += __shfl_xor_sync(0xffffffffu, pq[t], 2);
    }
    if ((lane & 3) == 0){
        #pragma unroll
        for (int mi = 0; mi < 2; ++mi)
            #pragma unroll
            for (int rh = 0; rh < 2; ++rh){
                int r = mi * 16 + rh * 8 + (lane >> 2);
                sred[r][wid] = ps[mi*2 + rh];
                qred[r][wid] = pq[mi*2 + rh];
            }
    }
    __syncthreads();

    // reduce 8 warp-partials per row -> mean, rstd
    {
        int row = tid >> 3, k = tid & 7;
        float s = sred[row][k], q = qred[row][k];
        s += __shfl_xor_sync(0xffffffffu, s, 1);
        s += __shfl_xor_sync(0xffffffffu, s, 2);
        s += __shfl_xor_sync(0xffffffffu, s, 4);
        q += __shfl_xor_sync(0xffffffffu, q, 1);
        q += __shfl_xor_sync(0xffffffffu, q, 2);
        q += __shfl_xor_sync(0xffffffffu, q, 4);
        if (k == 0){
            float mean = s * (1.f / 1024.f);
            float var  = q * (1.f / 1024.f) - mean * mean;
            smv[row][0] = mean;
            smv[row][1] = rsqrtf(var + 1e-5f);
        }
    }
    __syncthreads();

    // normalize + write
    #pragma unroll
    for (int mi = 0; mi < 2; ++mi){
        int r0 = mi * 16 + (lane >> 2);
        int r1 = r0 + 8;
        float mean0 = smv[r0][0], rstd0 = smv[r0][1];
        float mean1 = smv[r1][0], rstd1 = smv[r1][1];
        #pragma unroll
        for (int ni = 0; ni < 16; ++ni){
            int c = wid * 128 + ni * 8 + ((lane & 3) << 1);
            float2 g = ((const float2*)gamma)[c >> 1];
            float2 be = ((const float2*)beta)[c >> 1];
            float2 w0, w1;
            w0.x = (acc[mi][ni][0] - mean0) * rstd0 * g.x + be.x;
            w0.y = (acc[mi][ni][1] - mean0) * rstd0 * g.y + be.y;
            w1.x = (acc[mi][ni][2] - mean1) * rstd1 * g.x + be.x;
            w1.y = (acc[mi][ni][3] - mean1) * rstd1 * g.y + be.y;
            *(float2*)(out + (size_t)(m0 + r0) * FDIM + c) = w0;
            *(float2*)(out + (size_t)(m0 + r1) * FDIM + c) = w1;
        }
    }
}

// ---------------------------------------------------------------------------
// Launch
// ---------------------------------------------------------------------------
extern "C" void kernel_launch(void* const* d_in, const int* in_sizes, int n_in,
                              void* d_out, int out_size)
{
    (void)in_sizes; (void)n_in; (void)out_size;
    const float* x     = (const float*)d_in[0];
    const float* Wq    = (const float*)d_in[1];
    const float* bq    = (const float*)d_in[2];
    const float* Wk    = (const float*)d_in[3];
    const float* bk    = (const float*)d_in[4];
    const float* Wv    = (const float*)d_in[5];
    const float* bv    = (const float*)d_in[6];
    const float* Wo    = (const float*)d_in[7];
    const float* bo    = (const float*)d_in[8];
    const float* gamma = (const float*)d_in[9];
    const float* beta  = (const float*)d_in[10];
    float* out = (float*)d_out;

    cudaFuncSetAttribute(gemm1_kernel, cudaFuncAttributeMaxDynamicSharedMemorySize, GEMM_DSMEM);
    cudaFuncSetAttribute(gemm2_ln_kernel, cudaFuncAttributeMaxDynamicSharedMemorySize, G2_DSMEM);
    cudaFuncSetAttribute(attn_kernel, cudaFuncAttributeMaxDynamicSharedMemorySize, ATTN_DSMEM);

    convx_kernel<<<4096, 256>>>(x, bq, bk, bv);
    transw_kernel<<<dim3(32, 32, 4), dim3(32, 8)>>>(Wq, Wk, Wv, Wo);
    gemm1_kernel<<<dim3(NQKV / BN, TOKENS / BM), 256, GEMM_DSMEM>>>();
    attn_kernel<<<TOKENS / 8, 256, ATTN_DSMEM>>>();
    gemm2_ln_kernel<<<TOKENS / G2_BM, 256, G2_DSMEM>>>(bo, gamma, beta, out);
}

// round 5
// speedup vs baseline: 1.1379x; 1.1379x over previous
#include <cuda_runtime.h>
#include <cuda_fp16.h>
#include <cstdint>

// Problem constants
#define TOKENS 32768          // B*S = 16*2048
#define FDIM   1024
#define NQKV   3072
#define NHEAD  16
#define DHEAD  64

// ---------------------------------------------------------------------------
// Scratch (device globals; no allocations allowed)
// ---------------------------------------------------------------------------
__device__ __align__(16) half  g_X16 [(size_t)TOKENS * FDIM];   // x in fp16
__device__ __align__(16) half  g_Wqkv[(size_t)NQKV * FDIM];     // [N=3072, K=1024] transposed
__device__ __align__(16) half  g_Wo16[(size_t)FDIM * FDIM];     // [N=1024, K=1024] transposed
__device__ float               g_bqkv[NQKV];                    // packed biases
__device__ __align__(16) half  g_QKV [(size_t)TOKENS * NQKV];   // q,k,v per token
__device__ __align__(16) half  g_Attn[(size_t)TOKENS * FDIM];   // attention output
__device__ __align__(16) float g_Z   [(size_t)TOKENS * FDIM];   // pre-LN output

// ---------------------------------------------------------------------------
// PTX helpers
// ---------------------------------------------------------------------------
__device__ __forceinline__ void cp_async16(void* dst, const void* src){
    unsigned s = (unsigned)__cvta_generic_to_shared(dst);
    asm volatile("cp.async.cg.shared.global [%0], [%1], 16;\n" :: "r"(s), "l"(src));
}
__device__ __forceinline__ void cp_commit(){ asm volatile("cp.async.commit_group;\n"); }
template<int N>
__device__ __forceinline__ void cp_wait(){ asm volatile("cp.async.wait_group %0;\n" :: "n"(N)); }

__device__ __forceinline__ void ldsm_x4(uint32_t* r, uint32_t addr){
    asm volatile("ldmatrix.sync.aligned.m8n8.x4.shared.b16 {%0,%1,%2,%3}, [%4];\n"
        : "=r"(r[0]), "=r"(r[1]), "=r"(r[2]), "=r"(r[3]) : "r"(addr));
}
__device__ __forceinline__ void mma16816(float* c, const uint32_t* a, const uint32_t* b){
    asm volatile("mma.sync.aligned.m16n8k16.row.col.f32.f16.f16.f32 "
        "{%0,%1,%2,%3}, {%4,%5,%6,%7}, {%8,%9}, {%0,%1,%2,%3};\n"
        : "+f"(c[0]), "+f"(c[1]), "+f"(c[2]), "+f"(c[3])
        : "r"(a[0]), "r"(a[1]), "r"(a[2]), "r"(a[3]), "r"(b[0]), "r"(b[1]));
}

// ---------------------------------------------------------------------------
// Convert x fp32 -> fp16, and pack biases
// ---------------------------------------------------------------------------
__global__ void __launch_bounds__(256) convx_kernel(const float* __restrict__ x,
    const float* __restrict__ bq, const float* __restrict__ bk, const float* __restrict__ bv)
{
    const size_t n4 = (size_t)TOKENS * FDIM / 4;
    size_t gid = (size_t)blockIdx.x * blockDim.x + threadIdx.x;
    size_t stride = (size_t)gridDim.x * blockDim.x;
    for (size_t i = gid; i < n4; i += stride){
        float4 v = ((const float4*)x)[i];
        ((half2*)g_X16)[2*i]   = __floats2half2_rn(v.x, v.y);
        ((half2*)g_X16)[2*i+1] = __floats2half2_rn(v.z, v.w);
    }
    if (gid < NQKV){
        g_bqkv[gid] = (gid < 1024) ? bq[gid] : (gid < 2048) ? bk[gid - 1024] : bv[gid - 2048];
    }
}

// ---------------------------------------------------------------------------
// Tiled transpose: W[k][n] fp32 -> Wt[n][k] fp16.  z: 0..2 -> Wqkv rows, 3 -> Wo
// ---------------------------------------------------------------------------
__global__ void __launch_bounds__(256) transw_kernel(
    const float* __restrict__ Wq, const float* __restrict__ Wk,
    const float* __restrict__ Wv, const float* __restrict__ Wo)
{
    __shared__ float t[32][33];
    const int z = blockIdx.z;
    const float* src = (z == 0) ? Wq : (z == 1) ? Wk : (z == 2) ? Wv : Wo;
    const int k0 = blockIdx.y * 32, n0 = blockIdx.x * 32;
    const int tx = threadIdx.x, ty = threadIdx.y;   // 32 x 8
    #pragma unroll
    for (int i = 0; i < 4; ++i)
        t[ty + i * 8][tx] = src[(size_t)(k0 + ty + i * 8) * FDIM + n0 + tx];
    __syncthreads();
    half* dst = (z < 3) ? (g_Wqkv + (size_t)z * FDIM * FDIM) : g_Wo16;
    #pragma unroll
    for (int i = 0; i < 4; ++i)
        dst[(size_t)(n0 + ty + i * 8) * FDIM + k0 + tx] = __float2half_rn(t[tx][ty + i * 8]);
}

// ---------------------------------------------------------------------------
// HMMA GEMM: C[M,NTOT] = A[M,1024] * B[NTOT,1024]^T + bias
//   CTA tile 128x256, 8 warps (2x4), warp tile 64x64, BK=64, 4-stage ring.
// MODE 0: A=g_X16, B=g_Wqkv, C=g_QKV (half), bias=g_bqkv
// MODE 1: A=g_Attn, B=g_Wo16, C=g_Z (float), bias=bias_ext
// ---------------------------------------------------------------------------
#define BM 128
#define BN 256
#define BK 64
#define SROW 72
#define A_ST_BYTES (BM * SROW * 2)
#define B_ST_BYTES (BN * SROW * 2)
#define STAGE_BYTES (A_ST_BYTES + B_ST_BYTES)
#define NSTAGES 4
#define NKBLK (FDIM / BK)
#define GEMM_DSMEM (NSTAGES * STAGE_BYTES)

template<int MODE>
__global__ void __launch_bounds__(256, 1) gemm_hmma_kernel(const float* __restrict__ bias_ext)
{
    constexpr int NTOT = (MODE == 0) ? NQKV : FDIM;
    const half* __restrict__ A  = (MODE == 0) ? g_X16 : g_Attn;
    const half* __restrict__ Bw = (MODE == 0) ? g_Wqkv : g_Wo16;

    extern __shared__ __align__(16) half sm[];

    const int tid  = threadIdx.x;
    const int lane = tid & 31;
    const int wid  = tid >> 5;
    const int wm   = wid & 1;
    const int wn   = wid >> 1;
    const int m0 = blockIdx.y * BM;
    const int n0 = blockIdx.x * BN;

    const half* Abase = A  + (size_t)m0 * FDIM;
    const half* Bbase = Bw + (size_t)n0 * FDIM;

    float acc[4][8][4];
    #pragma unroll
    for (int mi = 0; mi < 4; ++mi)
        #pragma unroll
        for (int ni = 0; ni < 8; ++ni)
            #pragma unroll
            for (int t = 0; t < 4; ++t) acc[mi][ni][t] = 0.f;

    auto load_stage = [&](int s){
        const int buf = s & (NSTAGES - 1);
        half* as = sm + (size_t)buf * (STAGE_BYTES / 2);
        half* bs = as + (A_ST_BYTES / 2);
        const half* Asrc = Abase + s * BK;
        const half* Bsrc = Bbase + s * BK;
        #pragma unroll
        for (int i = 0; i < 4; ++i){
            int idx = tid + i * 256;
            int r = idx >> 3, c = idx & 7;
            cp_async16(as + r * SROW + c * 8, Asrc + (size_t)r * FDIM + c * 8);
        }
        #pragma unroll
        for (int i = 0; i < 8; ++i){
            int idx = tid + i * 256;
            int r = idx >> 3, c = idx & 7;
            cp_async16(bs + r * SROW + c * 8, Bsrc + (size_t)r * FDIM + c * 8);
        }
        cp_commit();
    };

    load_stage(0); load_stage(1); load_stage(2);

    const int a_row = wm * 64 + (lane & 15);
    const int a_colb = (lane >> 4) << 3;
    const int b_row = wn * 64 + (lane & 7) + ((lane >> 4) << 3);
    const int b_colb = ((lane >> 3) & 1) << 3;

    for (int s = 0; s < NKBLK; ++s){
        const int rem = (NKBLK - 1) - s;
        if (rem >= 2)      cp_wait<2>();
        else if (rem == 1) cp_wait<1>();
        else               cp_wait<0>();
        __syncthreads();

        if (s + 3 < NKBLK) load_stage(s + 3);

        const int buf = s & (NSTAGES - 1);
        const half* as = sm + (size_t)buf * (STAGE_BYTES / 2);
        const half* bs = as + (A_ST_BYTES / 2);
        const uint32_t aB = (uint32_t)__cvta_generic_to_shared(as);
        const uint32_t bB = (uint32_t)__cvta_generic_to_shared(bs);

        #pragma unroll
        for (int kk = 0; kk < 4; ++kk){
            const int k16 = kk * 16;
            uint32_t a[4][4], b[8][2];
            #pragma unroll
            for (int mi = 0; mi < 4; ++mi){
                uint32_t addr = aB + (uint32_t)(((a_row + mi * 16) * SROW + k16 + a_colb) * 2);
                ldsm_x4(&a[mi][0], addr);
            }
            #pragma unroll
            for (int nb = 0; nb < 4; ++nb){
                uint32_t addr = bB + (uint32_t)(((b_row + nb * 16) * SROW + k16 + b_colb) * 2);
                uint32_t r[4];
                ldsm_x4(r, addr);
                b[nb * 2][0] = r[0];     b[nb * 2][1] = r[1];
                b[nb * 2 + 1][0] = r[2]; b[nb * 2 + 1][1] = r[3];
            }
            #pragma unroll
            for (int mi = 0; mi < 4; ++mi)
                #pragma unroll
                for (int ni = 0; ni < 8; ++ni)
                    mma16816(acc[mi][ni], a[mi], b[ni]);
        }
    }

    const float* bias = (MODE == 0) ? g_bqkv : bias_ext;
    #pragma unroll
    for (int mi = 0; mi < 4; ++mi){
        #pragma unroll
        for (int ni = 0; ni < 8; ++ni){
            int r = m0 + wm * 64 + mi * 16 + (lane >> 2);
            int c = n0 + wn * 64 + ni * 8 + ((lane & 3) << 1);
            float b0 = bias[c], b1 = bias[c + 1];
            float v0 = acc[mi][ni][0] + b0, v1 = acc[mi][ni][1] + b1;
            float v2 = acc[mi][ni][2] + b0, v3 = acc[mi][ni][3] + b1;
            if constexpr (MODE == 0){
                *(half2*)(g_QKV + (size_t)r * NTOT + c)       = __floats2half2_rn(v0, v1);
                *(half2*)(g_QKV + (size_t)(r + 8) * NTOT + c) = __floats2half2_rn(v2, v3);
            } else {
                *(float2*)(g_Z + (size_t)r * NTOT + c)       = make_float2(v0, v1);
                *(float2*)(g_Z + (size_t)(r + 8) * NTOT + c) = make_float2(v2, v3);
            }
        }
    }
}

// ---------------------------------------------------------------------------
// Per-token cross-head attention. 1 warp per token, 8 tokens per block.
// d-dimension processed in two 16-element halves to cut register pressure
// (qr/o are 32 regs instead of 64) -> 3 blocks/SM.
// SMEM per token (half2 units): q[16][32] at 0, k[16][34] at 512,
// v[16][34] at 1056 -> 1600 half2. k/v bank = (2g+d)&31, conflict-free.
// ---------------------------------------------------------------------------
#define ATTN_TOK_H2 1600
#define ATTN_DSMEM (8 * ATTN_TOK_H2 * 4)   // 51200 bytes

__global__ void __launch_bounds__(256, 3) attn_kernel(){
    extern __shared__ __align__(16) half2 sq[];
    const int tid = threadIdx.x, lane = tid & 31, w = tid >> 5;
    const size_t tok0 = (size_t)blockIdx.x * 8;

    // scatter-load 8 tokens x 1536 half2 into padded layout
    int off[6];
    #pragma unroll
    for (int c2 = 0; c2 < 6; ++c2){
        int j = tid + c2 * 256;
        int o;
        if (j < 512) o = j;
        else if (j < 1024){ int e = j - 512;  o = 512  + (e >> 5) * 34 + (e & 31); }
        else              { int e = j - 1024; o = 1056 + (e >> 5) * 34 + (e & 31); }
        off[c2] = o;
    }
    const half2* src = (const half2*)(g_QKV + tok0 * NQKV);
    #pragma unroll
    for (int t = 0; t < 8; ++t){
        const half2* s = src + (size_t)t * 1536;
        half2* dst = sq + t * ATTN_TOK_H2;
        #pragma unroll
        for (int c2 = 0; c2 < 6; ++c2)
            dst[off[c2]] = s[tid + c2 * 256];
    }
    __syncthreads();

    half2* base = sq + w * ATTN_TOK_H2;
    const half2* q2 = base;
    const half2* k2 = base + 512;
    const half2* v2 = base + 1056;
    const int h  = lane >> 1;
    const int gb = (lane & 1) << 3;

    // energies, accumulated over two d-halves (16 half2 each)
    float e[8] = {0.f, 0.f, 0.f, 0.f, 0.f, 0.f, 0.f, 0.f};
    #pragma unroll
    for (int half_ = 0; half_ < 2; ++half_){
        float2 qr[16];
        #pragma unroll
        for (int j = 0; j < 16; ++j){
            int d = (half_ * 16 + j + h) & 31;
            qr[j] = __half22float2(q2[h * 32 + d]);
        }
        #pragma unroll
        for (int gi = 0; gi < 8; ++gi){
            int g = gb + gi;
            float a = 0.f;
            #pragma unroll
            for (int j = 0; j < 16; ++j){
                int d = (half_ * 16 + j + h) & 31;
                float2 kf = __half22float2(k2[g * 34 + d]);
                a += qr[j].x * kf.x + qr[j].y * kf.y;
            }
            e[gi] += a;
        }
    }
    #pragma unroll
    for (int gi = 0; gi < 8; ++gi) e[gi] *= 0.125f;

    // softmax over 16 g's split across the lane pair
    float m = e[0];
    #pragma unroll
    for (int gi = 1; gi < 8; ++gi) m = fmaxf(m, e[gi]);
    m = fmaxf(m, __shfl_xor_sync(0xffffffffu, m, 1));
    float ssum = 0.f;
    #pragma unroll
    for (int gi = 0; gi < 8; ++gi){ e[gi] = __expf(e[gi] - m); ssum += e[gi]; }
    ssum += __shfl_xor_sync(0xffffffffu, ssum, 1);
    float inv = 1.f / ssum;
    #pragma unroll
    for (int gi = 0; gi < 8; ++gi) e[gi] *= inv;

    // output, two d-halves; even lanes stash into (dead) q region
    #pragma unroll
    for (int half_ = 0; half_ < 2; ++half_){
        float2 o[16];
        #pragma unroll
        for (int j = 0; j < 16; ++j) o[j] = make_float2(0.f, 0.f);
        #pragma unroll
        for (int gi = 0; gi < 8; ++gi){
            float p = e[gi];
            int g = gb + gi;
            #pragma unroll
            for (int j = 0; j < 16; ++j){
                int d = (half_ * 16 + j + h) & 31;
                float2 vf = __half22float2(v2[g * 34 + d]);
                o[j].x += p * vf.x; o[j].y += p * vf.y;
            }
        }
        #pragma unroll
        for (int j = 0; j < 16; ++j){
            o[j].x += __shfl_xor_sync(0xffffffffu, o[j].x, 1);
            o[j].y += __shfl_xor_sync(0xffffffffu, o[j].y, 1);
        }
        __syncwarp();
        half2* outs = base;
        if ((lane & 1) == 0){
            #pragma unroll
            for (int j = 0; j < 16; ++j){
                int d = (half_ * 16 + j + h) & 31;
                outs[h * 32 + d] = __floats2half2_rn(o[j].x, o[j].y);
            }
        }
    }
    __syncthreads();

    // coalesced store: 8 tokens x 1024 halfs
    float4* gout = (float4*)(g_Attn + tok0 * FDIM);
    #pragma unroll
    for (int i = 0; i < 4; ++i){
        int c = tid + i * 256;
        int tw = c >> 7, off4 = c & 127;
        const float4* p = (const float4*)(sq + tw * ATTN_TOK_H2);
        gout[c] = p[off4];
    }
}

// ---------------------------------------------------------------------------
// LayerNorm over F=1024, one block per row
// ---------------------------------------------------------------------------
__global__ void __launch_bounds__(256) ln_kernel(const float* __restrict__ gamma,
                                                 const float* __restrict__ beta,
                                                 float* __restrict__ out)
{
    const int row = blockIdx.x, t = threadIdx.x, lane = t & 31, wid = t >> 5;
    float4 v = ((const float4*)(g_Z + (size_t)row * FDIM))[t];
    float s = v.x + v.y + v.z + v.w;
    float q = v.x * v.x + v.y * v.y + v.z * v.z + v.w * v.w;
    #pragma unroll
    for (int o = 16; o > 0; o >>= 1){
        s += __shfl_xor_sync(0xffffffffu, s, o);
        q += __shfl_xor_sync(0xffffffffu, q, o);
    }
    __shared__ float ws[8], wq[8], mv[2];
    if (lane == 0){ ws[wid] = s; wq[wid] = q; }
    __syncthreads();
    if (t == 0){
        float S = 0.f, Q = 0.f;
        #pragma unroll
        for (int i = 0; i < 8; ++i){ S += ws[i]; Q += wq[i]; }
        float mean = S * (1.f / 1024.f);
        float var  = Q * (1.f / 1024.f) - mean * mean;
        mv[0] = mean; mv[1] = rsqrtf(var + 1e-5f);
    }
    __syncthreads();
    float mean = mv[0], rstd = mv[1];
    float4 g4 = ((const float4*)gamma)[t];
    float4 b4 = ((const float4*)beta)[t];
    float4 r;
    r.x = (v.x - mean) * rstd * g4.x + b4.x;
    r.y = (v.y - mean) * rstd * g4.y + b4.y;
    r.z = (v.z - mean) * rstd * g4.z + b4.z;
    r.w = (v.w - mean) * rstd * g4.w + b4.w;
    ((float4*)(out + (size_t)row * FDIM))[t] = r;
}

// ---------------------------------------------------------------------------
// Launch
// ---------------------------------------------------------------------------
extern "C" void kernel_launch(void* const* d_in, const int* in_sizes, int n_in,
                              void* d_out, int out_size)
{
    (void)in_sizes; (void)n_in; (void)out_size;
    const float* x     = (const float*)d_in[0];
    const float* Wq    = (const float*)d_in[1];
    const float* bq    = (const float*)d_in[2];
    const float* Wk    = (const float*)d_in[3];
    const float* bk    = (const float*)d_in[4];
    const float* Wv    = (const float*)d_in[5];
    const float* bv    = (const float*)d_in[6];
    const float* Wo    = (const float*)d_in[7];
    const float* bo    = (const float*)d_in[8];
    const float* gamma = (const float*)d_in[9];
    const float* beta  = (const float*)d_in[10];
    float* out = (float*)d_out;

    cudaFuncSetAttribute(gemm_hmma_kernel<0>, cudaFuncAttributeMaxDynamicSharedMemorySize, GEMM_DSMEM);
    cudaFuncSetAttribute(gemm_hmma_kernel<1>, cudaFuncAttributeMaxDynamicSharedMemorySize, GEMM_DSMEM);
    cudaFuncSetAttribute(attn_kernel, cudaFuncAttributeMaxDynamicSharedMemorySize, ATTN_DSMEM);

    convx_kernel<<<4096, 256>>>(x, bq, bk, bv);
    transw_kernel<<<dim3(32, 32, 4), dim3(32, 8)>>>(Wq, Wk, Wv, Wo);
    gemm_hmma_kernel<0><<<dim3(NQKV / BN, TOKENS / BM), 256, GEMM_DSMEM>>>(nullptr);
    attn_kernel<<<TOKENS / 8, 256, ATTN_DSMEM>>>();
    gemm_hmma_kernel<1><<<dim3(FDIM / BN, TOKENS / BM), 256, GEMM_DSMEM>>>(bo);
    ln_kernel<<<TOKENS, 256>>>(gamma, beta, out);
}

// round 7
// speedup vs baseline: 1.2211x; 1.0731x over previous
#include <cuda_runtime.h>
#include <cuda_fp16.h>
#include <cstdint>

// Problem constants
#define TOKENS 32768          // B*S = 16*2048
#define FDIM   1024
#define NQKV   3072
#define NHEAD  16
#define DHEAD  64

// ---------------------------------------------------------------------------
// Scratch (device globals; no allocations allowed)
// ---------------------------------------------------------------------------
__device__ __align__(16) half  g_X16 [(size_t)TOKENS * FDIM];   // x in fp16
__device__ __align__(16) half  g_Wqkv[(size_t)NQKV * FDIM];     // [N=3072, K=1024] transposed
__device__ __align__(16) half  g_Wo16[(size_t)FDIM * FDIM];     // [N=1024, K=1024] transposed
__device__ float               g_bqkv[NQKV];                    // packed biases
__device__ __align__(16) half  g_QKV [(size_t)TOKENS * NQKV];   // q,k,v per token
__device__ __align__(16) half  g_Attn[(size_t)TOKENS * FDIM];   // attention output
__device__ __align__(16) float g_Z   [(size_t)TOKENS * FDIM];   // pre-LN output

// ---------------------------------------------------------------------------
// PTX helpers
// ---------------------------------------------------------------------------
__device__ __forceinline__ void cp_async16(void* dst, const void* src){
    unsigned s = (unsigned)__cvta_generic_to_shared(dst);
    asm volatile("cp.async.cg.shared.global [%0], [%1], 16;\n" :: "r"(s), "l"(src));
}
__device__ __forceinline__ void cp_commit(){ asm volatile("cp.async.commit_group;\n"); }
template<int N>
__device__ __forceinline__ void cp_wait(){ asm volatile("cp.async.wait_group %0;\n" :: "n"(N)); }

__device__ __forceinline__ void ldsm_x4(uint32_t* r, uint32_t addr){
    asm volatile("ldmatrix.sync.aligned.m8n8.x4.shared.b16 {%0,%1,%2,%3}, [%4];\n"
        : "=r"(r[0]), "=r"(r[1]), "=r"(r[2]), "=r"(r[3]) : "r"(addr));
}
__device__ __forceinline__ void ldsm_x4_t(uint32_t* r, uint32_t addr){
    asm volatile("ldmatrix.sync.aligned.m8n8.x4.trans.shared.b16 {%0,%1,%2,%3}, [%4];\n"
        : "=r"(r[0]), "=r"(r[1]), "=r"(r[2]), "=r"(r[3]) : "r"(addr));
}
__device__ __forceinline__ void mma16816(float* c, const uint32_t* a, const uint32_t* b){
    asm volatile("mma.sync.aligned.m16n8k16.row.col.f32.f16.f16.f32 "
        "{%0,%1,%2,%3}, {%4,%5,%6,%7}, {%8,%9}, {%0,%1,%2,%3};\n"
        : "+f"(c[0]), "+f"(c[1]), "+f"(c[2]), "+f"(c[3])
        : "r"(a[0]), "r"(a[1]), "r"(a[2]), "r"(a[3]), "r"(b[0]), "r"(b[1]));
}
__device__ __forceinline__ uint32_t h2_to_u32(half2 h){
    uint32_t u;
    memcpy(&u, &h, 4);
    return u;
}

// ---------------------------------------------------------------------------
// Convert x fp32 -> fp16, and pack biases
// ---------------------------------------------------------------------------
__global__ void __launch_bounds__(256) convx_kernel(const float* __restrict__ x,
    const float* __restrict__ bq, const float* __restrict__ bk, const float* __restrict__ bv)
{
    const size_t n4 = (size_t)TOKENS * FDIM / 4;
    size_t gid = (size_t)blockIdx.x * blockDim.x + threadIdx.x;
    size_t stride = (size_t)gridDim.x * blockDim.x;
    for (size_t i = gid; i < n4; i += stride){
        float4 v = ((const float4*)x)[i];
        ((half2*)g_X16)[2*i]   = __floats2half2_rn(v.x, v.y);
        ((half2*)g_X16)[2*i+1] = __floats2half2_rn(v.z, v.w);
    }
    if (gid < NQKV){
        g_bqkv[gid] = (gid < 1024) ? bq[gid] : (gid < 2048) ? bk[gid - 1024] : bv[gid - 2048];
    }
}

// ---------------------------------------------------------------------------
// Tiled transpose: W[k][n] fp32 -> Wt[n][k] fp16.  z: 0..2 -> Wqkv rows, 3 -> Wo
// ---------------------------------------------------------------------------
__global__ void __launch_bounds__(256) transw_kernel(
    const float* __restrict__ Wq, const float* __restrict__ Wk,
    const float* __restrict__ Wv, const float* __restrict__ Wo)
{
    __shared__ float t[32][33];
    const int z = blockIdx.z;
    const float* src = (z == 0) ? Wq : (z == 1) ? Wk : (z == 2) ? Wv : Wo;
    const int k0 = blockIdx.y * 32, n0 = blockIdx.x * 32;
    const int tx = threadIdx.x, ty = threadIdx.y;   // 32 x 8
    #pragma unroll
    for (int i = 0; i < 4; ++i)
        t[ty + i * 8][tx] = src[(size_t)(k0 + ty + i * 8) * FDIM + n0 + tx];
    __syncthreads();
    half* dst = (z < 3) ? (g_Wqkv + (size_t)z * FDIM * FDIM) : g_Wo16;
    #pragma unroll
    for (int i = 0; i < 4; ++i)
        dst[(size_t)(n0 + ty + i * 8) * FDIM + k0 + tx] = __float2half_rn(t[tx][ty + i * 8]);
}

// ---------------------------------------------------------------------------
// HMMA GEMM: C[M,NTOT] = A[M,1024] * B[NTOT,1024]^T + bias
//   CTA tile 128x256, 8 warps (2x4), warp tile 64x64, BK=64, 4-stage ring.
// MODE 0: A=g_X16, B=g_Wqkv, C=g_QKV (half), bias=g_bqkv
// MODE 1: A=g_Attn, B=g_Wo16, C=g_Z (float), bias=bias_ext
// ---------------------------------------------------------------------------
#define BM 128
#define BN 256
#define BK 64
#define SROW 72
#define A_ST_BYTES (BM * SROW * 2)
#define B_ST_BYTES (BN * SROW * 2)
#define STAGE_BYTES (A_ST_BYTES + B_ST_BYTES)
#define NSTAGES 4
#define NKBLK (FDIM / BK)
#define GEMM_DSMEM (NSTAGES * STAGE_BYTES)

template<int MODE>
__global__ void __launch_bounds__(256, 1) gemm_hmma_kernel(const float* __restrict__ bias_ext)
{
    constexpr int NTOT = (MODE == 0) ? NQKV : FDIM;
    const half* __restrict__ A  = (MODE == 0) ? g_X16 : g_Attn;
    const half* __restrict__ Bw = (MODE == 0) ? g_Wqkv : g_Wo16;

    extern __shared__ __align__(16) half sm[];

    const int tid  = threadIdx.x;
    const int lane = tid & 31;
    const int wid  = tid >> 5;
    const int wm   = wid & 1;
    const int wn   = wid >> 1;
    const int m0 = blockIdx.y * BM;
    const int n0 = blockIdx.x * BN;

    const half* Abase = A  + (size_t)m0 * FDIM;
    const half* Bbase = Bw + (size_t)n0 * FDIM;

    float acc[4][8][4];
    #pragma unroll
    for (int mi = 0; mi < 4; ++mi)
        #pragma unroll
        for (int ni = 0; ni < 8; ++ni)
            #pragma unroll
            for (int t = 0; t < 4; ++t) acc[mi][ni][t] = 0.f;

    auto load_stage = [&](int s){
        const int buf = s & (NSTAGES - 1);
        half* as = sm + (size_t)buf * (STAGE_BYTES / 2);
        half* bs = as + (A_ST_BYTES / 2);
        const half* Asrc = Abase + s * BK;
        const half* Bsrc = Bbase + s * BK;
        #pragma unroll
        for (int i = 0; i < 4; ++i){
            int idx = tid + i * 256;
            int r = idx >> 3, c = idx & 7;
            cp_async16(as + r * SROW + c * 8, Asrc + (size_t)r * FDIM + c * 8);
        }
        #pragma unroll
        for (int i = 0; i < 8; ++i){
            int idx = tid + i * 256;
            int r = idx >> 3, c = idx & 7;
            cp_async16(bs + r * SROW + c * 8, Bsrc + (size_t)r * FDIM + c * 8);
        }
        cp_commit();
    };

    load_stage(0); load_stage(1); load_stage(2);

    const int a_row = wm * 64 + (lane & 15);
    const int a_colb = (lane >> 4) << 3;
    const int b_row = wn * 64 + (lane & 7) + ((lane >> 4) << 3);
    const int b_colb = ((lane >> 3) & 1) << 3;

    for (int s = 0; s < NKBLK; ++s){
        const int rem = (NKBLK - 1) - s;
        if (rem >= 2)      cp_wait<2>();
        else if (rem == 1) cp_wait<1>();
        else               cp_wait<0>();
        __syncthreads();

        if (s + 3 < NKBLK) load_stage(s + 3);

        const int buf = s & (NSTAGES - 1);
        const half* as = sm + (size_t)buf * (STAGE_BYTES / 2);
        const half* bs = as + (A_ST_BYTES / 2);
        const uint32_t aB = (uint32_t)__cvta_generic_to_shared(as);
        const uint32_t bB = (uint32_t)__cvta_generic_to_shared(bs);

        #pragma unroll
        for (int kk = 0; kk < 4; ++kk){
            const int k16 = kk * 16;
            uint32_t a[4][4], b[8][2];
            #pragma unroll
            for (int mi = 0; mi < 4; ++mi){
                uint32_t addr = aB + (uint32_t)(((a_row + mi * 16) * SROW + k16 + a_colb) * 2);
                ldsm_x4(&a[mi][0], addr);
            }
            #pragma unroll
            for (int nb = 0; nb < 4; ++nb){
                uint32_t addr = bB + (uint32_t)(((b_row + nb * 16) * SROW + k16 + b_colb) * 2);
                uint32_t r[4];
                ldsm_x4(r, addr);
                b[nb * 2][0] = r[0];     b[nb * 2][1] = r[1];
                b[nb * 2 + 1][0] = r[2]; b[nb * 2 + 1][1] = r[3];
            }
            #pragma unroll
            for (int mi = 0; mi < 4; ++mi)
                #pragma unroll
                for (int ni = 0; ni < 8; ++ni)
                    mma16816(acc[mi][ni], a[mi], b[ni]);
        }
    }

    const float* bias = (MODE == 0) ? g_bqkv : bias_ext;
    #pragma unroll
    for (int mi = 0; mi < 4; ++mi){
        #pragma unroll
        for (int ni = 0; ni < 8; ++ni){
            int r = m0 + wm * 64 + mi * 16 + (lane >> 2);
            int c = n0 + wn * 64 + ni * 8 + ((lane & 3) << 1);
            float b0 = bias[c], b1 = bias[c + 1];
            float v0 = acc[mi][ni][0] + b0, v1 = acc[mi][ni][1] + b1;
            float v2 = acc[mi][ni][2] + b0, v3 = acc[mi][ni][3] + b1;
            if constexpr (MODE == 0){
                *(half2*)(g_QKV + (size_t)r * NTOT + c)       = __floats2half2_rn(v0, v1);
                *(half2*)(g_QKV + (size_t)(r + 8) * NTOT + c) = __floats2half2_rn(v2, v3);
            } else {
                *(float2*)(g_Z + (size_t)r * NTOT + c)       = make_float2(v0, v1);
                *(float2*)(g_Z + (size_t)(r + 8) * NTOT + c) = make_float2(v2, v3);
            }
        }
    }
}

// ---------------------------------------------------------------------------
// Tensor-core per-token attention. 1 warp per token, 8 tokens per block.
// Token SMEM: 48 rows (q 0-15, k 16-31, v 32-47) x 72-half padded stride.
//   E(16x16) = Q·K^T via 8 HMMA; softmax in C-fragments (2 shfls);
//   P fragments = cvt(E frags) in place; O(16x64) = P·V via 8 HMMA
//   with V loaded through ldsm.trans. Output staged in dead Q rows.
// ---------------------------------------------------------------------------
#define ATOK_ROWS 48
#define ATOK_H (ATOK_ROWS * 72)            // 3456 halfs per token
#define ATTN_DSMEM (8 * ATOK_H * 2)        // 55296 bytes

__global__ void __launch_bounds__(256) attn_mma_kernel(){
    extern __shared__ __align__(16) half sm_a[];
    const int tid = threadIdx.x, lane = tid & 31, w = tid >> 5;
    const size_t tok0 = (size_t)blockIdx.x * 8;

    // cooperative load: 8 tokens x 3072 halfs -> 48 rows x 72-stride each
    {
        const float4* src = (const float4*)(g_QKV + tok0 * NQKV);
        #pragma unroll
        for (int i = 0; i < 12; ++i){
            int idx = tid + i * 256;          // 0..3071 chunks of 8 halfs
            int tok = idx / 384, j = idx - tok * 384;
            int row = j >> 3, c = j & 7;
            *(float4*)(sm_a + tok * ATOK_H + row * 72 + c * 8) = src[(size_t)tok * 384 + j];
        }
    }
    __syncthreads();

    half* base = sm_a + w * ATOK_H;
    const uint32_t sb = (uint32_t)__cvta_generic_to_shared(base);

    // ---- E = Q K^T  (m16 n16 k64) ----
    float e0[4] = {0,0,0,0}, e1[4] = {0,0,0,0};
    {
        const int q_row  = lane & 15;
        const int q_colb = (lane >> 4) << 3;
        const int k_row  = 16 + (lane & 7) + ((lane >> 4) << 3);
        const int k_colb = ((lane >> 3) & 1) << 3;
        #pragma unroll
        for (int kc = 0; kc < 4; ++kc){
            const int k16 = kc * 16;
            uint32_t qa[4], kr[4];
            ldsm_x4(qa, sb + (uint32_t)((q_row * 72 + k16 + q_colb) * 2));
            ldsm_x4(kr, sb + (uint32_t)((k_row * 72 + k16 + k_colb) * 2));
            mma16816(e0, qa, &kr[0]);     // cols g 0-7
            mma16816(e1, qa, &kr[2]);     // cols g 8-15
        }
    }

    // ---- softmax over g (16 cols), rows r=lane>>2 and r+8 ----
    // row r owns e0[0],e0[1],e1[0],e1[1]; row r+8 owns e0[2],e0[3],e1[2],e1[3]
    {
        const float sc = 0.125f;   // 1/sqrt(64)
        e0[0]*=sc; e0[1]*=sc; e0[2]*=sc; e0[3]*=sc;
        e1[0]*=sc; e1[1]*=sc; e1[2]*=sc; e1[3]*=sc;
        float mA = fmaxf(fmaxf(e0[0], e0[1]), fmaxf(e1[0], e1[1]));
        float mB = fmaxf(fmaxf(e0[2], e0[3]), fmaxf(e1[2], e1[3]));
        mA = fmaxf(mA, __shfl_xor_sync(0xffffffffu, mA, 1));
        mA = fmaxf(mA, __shfl_xor_sync(0xffffffffu, mA, 2));
        mB = fmaxf(mB, __shfl_xor_sync(0xffffffffu, mB, 1));
        mB = fmaxf(mB, __shfl_xor_sync(0xffffffffu, mB, 2));
        e0[0] = __expf(e0[0] - mA); e0[1] = __expf(e0[1] - mA);
        e1[0] = __expf(e1[0] - mA); e1[1] = __expf(e1[1] - mA);
        e0[2] = __expf(e0[2] - mB); e0[3] = __expf(e0[3] - mB);
        e1[2] = __expf(e1[2] - mB); e1[3] = __expf(e1[3] - mB);
        float sA = e0[0] + e0[1] + e1[0] + e1[1];
        float sB = e0[2] + e0[3] + e1[2] + e1[3];
        sA += __shfl_xor_sync(0xffffffffu, sA, 1);
        sA += __shfl_xor_sync(0xffffffffu, sA, 2);
        sB += __shfl_xor_sync(0xffffffffu, sB, 1);
        sB += __shfl_xor_sync(0xffffffffu, sB, 2);
        float iA = 1.f / sA, iB = 1.f / sB;
        e0[0]*=iA; e0[1]*=iA; e1[0]*=iA; e1[1]*=iA;
        e0[2]*=iB; e0[3]*=iB; e1[2]*=iB; e1[3]*=iB;
    }

    // ---- P fragments (A operand of O = P V): direct register reuse ----
    uint32_t pa[4];
    pa[0] = h2_to_u32(__floats2half2_rn(e0[0], e0[1]));  // (r,   k=g 0-7 slot)
    pa[1] = h2_to_u32(__floats2half2_rn(e0[2], e0[3]));  // (r+8, k=g 0-7 slot)
    pa[2] = h2_to_u32(__floats2half2_rn(e1[0], e1[1]));  // (r,   k=g 8-15 slot)
    pa[3] = h2_to_u32(__floats2half2_rn(e1[2], e1[3]));  // (r+8, k=g 8-15 slot)

    // ---- O = P V  (m16 n64 k16), V via ldsm.trans ----
    float o[8][4];
    #pragma unroll
    for (int nt = 0; nt < 8; ++nt){ o[nt][0]=0; o[nt][1]=0; o[nt][2]=0; o[nt][3]=0; }
    {
        const int v_row = 32 + (lane & 15);
        #pragma unroll
        for (int i = 0; i < 4; ++i){
            const int db = i * 16;
            uint32_t vr[4];
            ldsm_x4_t(vr, sb + (uint32_t)((v_row * 72 + db + ((lane >> 4) << 3)) * 2));
            mma16816(o[i * 2],     pa, &vr[0]);   // d cols db..db+7
            mma16816(o[i * 2 + 1], pa, &vr[2]);   // d cols db+8..db+15
        }
    }

    // ---- stage O into dead Q rows (0-15), then coalesced global store ----
    {
        const int r = lane >> 2;
        const int c2 = (lane & 3) << 1;
        #pragma unroll
        for (int nt = 0; nt < 8; ++nt){
            *(half2*)(base + r * 72 + nt * 8 + c2)       = __floats2half2_rn(o[nt][0], o[nt][1]);
            *(half2*)(base + (r + 8) * 72 + nt * 8 + c2) = __floats2half2_rn(o[nt][2], o[nt][3]);
        }
    }
    __syncthreads();

    {
        float4* gout = (float4*)(g_Attn + tok0 * FDIM);
        #pragma unroll
        for (int i = 0; i < 4; ++i){
            int idx = tid + i * 256;          // 0..1023 chunks of 8 halfs
            int tok = idx >> 7, j = idx & 127;
            int row = j >> 3, c = j & 7;
            gout[(size_t)tok * 128 + j] = *(const float4*)(sm_a + tok * ATOK_H + row * 72 + c * 8);
        }
    }
}

// ---------------------------------------------------------------------------
// LayerNorm over F=1024, one block per row
// ---------------------------------------------------------------------------
__global__ void __launch_bounds__(256) ln_kernel(const float* __restrict__ gamma,
                                                 const float* __restrict__ beta,
                                                 float* __restrict__ out)
{
    const int row = blockIdx.x, t = threadIdx.x, lane = t & 31, wid = t >> 5;
    float4 v = ((const float4*)(g_Z + (size_t)row * FDIM))[t];
    float s = v.x + v.y + v.z + v.w;
    float q = v.x * v.x + v.y * v.y + v.z * v.z + v.w * v.w;
    #pragma unroll
    for (int o = 16; o > 0; o >>= 1){
        s += __shfl_xor_sync(0xffffffffu, s, o);
        q += __shfl_xor_sync(0xffffffffu, q, o);
    }
    __shared__ float ws[8], wq[8], mv[2];
    if (lane == 0){ ws[wid] = s; wq[wid] = q; }
    __syncthreads();
    if (t == 0){
        float S = 0.f, Q = 0.f;
        #pragma unroll
        for (int i = 0; i < 8; ++i){ S += ws[i]; Q += wq[i]; }
        float mean = S * (1.f / 1024.f);
        float var  = Q * (1.f / 1024.f) - mean * mean;
        mv[0] = mean; mv[1] = rsqrtf(var + 1e-5f);
    }
    __syncthreads();
    float mean = mv[0], rstd = mv[1];
    float4 g4 = ((const float4*)gamma)[t];
    float4 b4 = ((const float4*)beta)[t];
    float4 r;
    r.x = (v.x - mean) * rstd * g4.x + b4.x;
    r.y = (v.y - mean) * rstd * g4.y + b4.y;
    r.z = (v.z - mean) * rstd * g4.z + b4.z;
    r.w = (v.w - mean) * rstd * g4.w + b4.w;
    ((float4*)(out + (size_t)row * FDIM))[t] = r;
}

// ---------------------------------------------------------------------------
// Launch
// ---------------------------------------------------------------------------
extern "C" void kernel_launch(void* const* d_in, const int* in_sizes, int n_in,
                              void* d_out, int out_size)
{
    (void)in_sizes; (void)n_in; (void)out_size;
    const float* x     = (const float*)d_in[0];
    const float* Wq    = (const float*)d_in[1];
    const float* bq    = (const float*)d_in[2];
    const float* Wk    = (const float*)d_in[3];
    const float* bk    = (const float*)d_in[4];
    const float* Wv    = (const float*)d_in[5];
    const float* bv    = (const float*)d_in[6];
    const float* Wo    = (const float*)d_in[7];
    const float* bo    = (const float*)d_in[8];
    const float* gamma = (const float*)d_in[9];
    const float* beta  = (const float*)d_in[10];
    float* out = (float*)d_out;

    cudaFuncSetAttribute(gemm_hmma_kernel<0>, cudaFuncAttributeMaxDynamicSharedMemorySize, GEMM_DSMEM);
    cudaFuncSetAttribute(gemm_hmma_kernel<1>, cudaFuncAttributeMaxDynamicSharedMemorySize, GEMM_DSMEM);
    cudaFuncSetAttribute(attn_mma_kernel, cudaFuncAttributeMaxDynamicSharedMemorySize, ATTN_DSMEM);

    convx_kernel<<<4096, 256>>>(x, bq, bk, bv);
    transw_kernel<<<dim3(32, 32, 4), dim3(32, 8)>>>(Wq, Wk, Wv, Wo);
    gemm_hmma_kernel<0><<<dim3(NQKV / BN, TOKENS / BM), 256, GEMM_DSMEM>>>(nullptr);
    attn_mma_kernel<<<TOKENS / 8, 256, ATTN_DSMEM>>>();
    gemm_hmma_kernel<1><<<dim3(FDIM / BN, TOKENS / BM), 256, GEMM_DSMEM>>>(bo);
    ln_kernel<<<TOKENS, 256>>>(gamma, beta, out);
}

// round 8
// speedup vs baseline: 1.2355x; 1.0118x over previous
#include <cuda_runtime.h>
#include <cuda_fp16.h>
#include <cstdint>

// Problem constants
#define TOKENS 32768          // B*S = 16*2048
#define FDIM   1024
#define NQKV   3072
#define NHEAD  16
#define DHEAD  64

// ---------------------------------------------------------------------------
// Scratch (device globals; no allocations allowed)
// ---------------------------------------------------------------------------
__device__ __align__(16) half  g_X16 [(size_t)TOKENS * FDIM];   // x in fp16
__device__ __align__(16) half  g_Wqkv[(size_t)NQKV * FDIM];     // [N=3072, K=1024] transposed
__device__ __align__(16) half  g_Wo16[(size_t)FDIM * FDIM];     // [N=1024, K=1024] transposed
__device__ float               g_bqkv[NQKV];                    // packed biases
__device__ __align__(16) half  g_QKV [(size_t)TOKENS * NQKV];   // q,k,v per token
__device__ __align__(16) half  g_Attn[(size_t)TOKENS * FDIM];   // attention output
__device__ __align__(16) half  g_Z16 [(size_t)TOKENS * FDIM];   // pre-LN output (fp16)

// ---------------------------------------------------------------------------
// PTX helpers
// ---------------------------------------------------------------------------
__device__ __forceinline__ void cp_async16(void* dst, const void* src){
    unsigned s = (unsigned)__cvta_generic_to_shared(dst);
    asm volatile("cp.async.cg.shared.global [%0], [%1], 16;\n" :: "r"(s), "l"(src));
}
__device__ __forceinline__ void cp_commit(){ asm volatile("cp.async.commit_group;\n"); }
template<int N>
__device__ __forceinline__ void cp_wait(){ asm volatile("cp.async.wait_group %0;\n" :: "n"(N)); }

__device__ __forceinline__ void ldsm_x4(uint32_t* r, uint32_t addr){
    asm volatile("ldmatrix.sync.aligned.m8n8.x4.shared.b16 {%0,%1,%2,%3}, [%4];\n"
        : "=r"(r[0]), "=r"(r[1]), "=r"(r[2]), "=r"(r[3]) : "r"(addr));
}
__device__ __forceinline__ void ldsm_x4_t(uint32_t* r, uint32_t addr){
    asm volatile("ldmatrix.sync.aligned.m8n8.x4.trans.shared.b16 {%0,%1,%2,%3}, [%4];\n"
        : "=r"(r[0]), "=r"(r[1]), "=r"(r[2]), "=r"(r[3]) : "r"(addr));
}
__device__ __forceinline__ void mma16816(float* c, const uint32_t* a, const uint32_t* b){
    asm volatile("mma.sync.aligned.m16n8k16.row.col.f32.f16.f16.f32 "
        "{%0,%1,%2,%3}, {%4,%5,%6,%7}, {%8,%9}, {%0,%1,%2,%3};\n"
        : "+f"(c[0]), "+f"(c[1]), "+f"(c[2]), "+f"(c[3])
        : "r"(a[0]), "r"(a[1]), "r"(a[2]), "r"(a[3]), "r"(b[0]), "r"(b[1]));
}
__device__ __forceinline__ uint32_t h2_to_u32(half2 h){
    uint32_t u;
    memcpy(&u, &h, 4);
    return u;
}

// ---------------------------------------------------------------------------
// Convert x fp32 -> fp16, and pack biases
// ---------------------------------------------------------------------------
__global__ void __launch_bounds__(256) convx_kernel(const float* __restrict__ x,
    const float* __restrict__ bq, const float* __restrict__ bk, const float* __restrict__ bv)
{
    const size_t n4 = (size_t)TOKENS * FDIM / 4;
    size_t gid = (size_t)blockIdx.x * blockDim.x + threadIdx.x;
    size_t stride = (size_t)gridDim.x * blockDim.x;
    for (size_t i = gid; i < n4; i += stride){
        float4 v = ((const float4*)x)[i];
        ((half2*)g_X16)[2*i]   = __floats2half2_rn(v.x, v.y);
        ((half2*)g_X16)[2*i+1] = __floats2half2_rn(v.z, v.w);
    }
    if (gid < NQKV){
        g_bqkv[gid] = (gid < 1024) ? bq[gid] : (gid < 2048) ? bk[gid - 1024] : bv[gid - 2048];
    }
}

// ---------------------------------------------------------------------------
// Tiled transpose: W[k][n] fp32 -> Wt[n][k] fp16.  z: 0..2 -> Wqkv rows, 3 -> Wo
// ---------------------------------------------------------------------------
__global__ void __launch_bounds__(256) transw_kernel(
    const float* __restrict__ Wq, const float* __restrict__ Wk,
    const float* __restrict__ Wv, const float* __restrict__ Wo)
{
    __shared__ float t[32][33];
    const int z = blockIdx.z;
    const float* src = (z == 0) ? Wq : (z == 1) ? Wk : (z == 2) ? Wv : Wo;
    const int k0 = blockIdx.y * 32, n0 = blockIdx.x * 32;
    const int tx = threadIdx.x, ty = threadIdx.y;   // 32 x 8
    #pragma unroll
    for (int i = 0; i < 4; ++i)
        t[ty + i * 8][tx] = src[(size_t)(k0 + ty + i * 8) * FDIM + n0 + tx];
    __syncthreads();
    half* dst = (z < 3) ? (g_Wqkv + (size_t)z * FDIM * FDIM) : g_Wo16;
    #pragma unroll
    for (int i = 0; i < 4; ++i)
        dst[(size_t)(n0 + ty + i * 8) * FDIM + k0 + tx] = __float2half_rn(t[tx][ty + i * 8]);
}

// ---------------------------------------------------------------------------
// HMMA GEMM: C[M,NTOT] = A[M,1024] * B[NTOT,1024]^T + bias
//   CTA tile 128x256, 8 warps (2x4), warp tile 64x64, BK=64, 4-stage ring.
// MODE 0: A=g_X16, B=g_Wqkv, C=g_QKV (half), bias=g_bqkv
// MODE 1: A=g_Attn, B=g_Wo16, C=g_Z16 (half), bias=bias_ext
// ---------------------------------------------------------------------------
#define BM 128
#define BN 256
#define BK 64
#define SROW 72
#define A_ST_BYTES (BM * SROW * 2)
#define B_ST_BYTES (BN * SROW * 2)
#define STAGE_BYTES (A_ST_BYTES + B_ST_BYTES)
#define NSTAGES 4
#define NKBLK (FDIM / BK)
#define GEMM_DSMEM (NSTAGES * STAGE_BYTES)

template<int MODE>
__global__ void __launch_bounds__(256, 1) gemm_hmma_kernel(const float* __restrict__ bias_ext)
{
    constexpr int NTOT = (MODE == 0) ? NQKV : FDIM;
    const half* __restrict__ A  = (MODE == 0) ? g_X16 : g_Attn;
    const half* __restrict__ Bw = (MODE == 0) ? g_Wqkv : g_Wo16;

    extern __shared__ __align__(16) half sm[];

    const int tid  = threadIdx.x;
    const int lane = tid & 31;
    const int wid  = tid >> 5;
    const int wm   = wid & 1;
    const int wn   = wid >> 1;
    const int m0 = blockIdx.y * BM;
    const int n0 = blockIdx.x * BN;

    const half* Abase = A  + (size_t)m0 * FDIM;
    const half* Bbase = Bw + (size_t)n0 * FDIM;

    float acc[4][8][4];
    #pragma unroll
    for (int mi = 0; mi < 4; ++mi)
        #pragma unroll
        for (int ni = 0; ni < 8; ++ni)
            #pragma unroll
            for (int t = 0; t < 4; ++t) acc[mi][ni][t] = 0.f;

    auto load_stage = [&](int s){
        const int buf = s & (NSTAGES - 1);
        half* as = sm + (size_t)buf * (STAGE_BYTES / 2);
        half* bs = as + (A_ST_BYTES / 2);
        const half* Asrc = Abase + s * BK;
        const half* Bsrc = Bbase + s * BK;
        #pragma unroll
        for (int i = 0; i < 4; ++i){
            int idx = tid + i * 256;
            int r = idx >> 3, c = idx & 7;
            cp_async16(as + r * SROW + c * 8, Asrc + (size_t)r * FDIM + c * 8);
        }
        #pragma unroll
        for (int i = 0; i < 8; ++i){
            int idx = tid + i * 256;
            int r = idx >> 3, c = idx & 7;
            cp_async16(bs + r * SROW + c * 8, Bsrc + (size_t)r * FDIM + c * 8);
        }
        cp_commit();
    };

    load_stage(0); load_stage(1); load_stage(2);

    const int a_row = wm * 64 + (lane & 15);
    const int a_colb = (lane >> 4) << 3;
    const int b_row = wn * 64 + (lane & 7) + ((lane >> 4) << 3);
    const int b_colb = ((lane >> 3) & 1) << 3;

    for (int s = 0; s < NKBLK; ++s){
        const int rem = (NKBLK - 1) - s;
        if (rem >= 2)      cp_wait<2>();
        else if (rem == 1) cp_wait<1>();
        else               cp_wait<0>();
        __syncthreads();

        if (s + 3 < NKBLK) load_stage(s + 3);

        const int buf = s & (NSTAGES - 1);
        const half* as = sm + (size_t)buf * (STAGE_BYTES / 2);
        const half* bs = as + (A_ST_BYTES / 2);
        const uint32_t aB = (uint32_t)__cvta_generic_to_shared(as);
        const uint32_t bB = (uint32_t)__cvta_generic_to_shared(bs);

        #pragma unroll
        for (int kk = 0; kk < 4; ++kk){
            const int k16 = kk * 16;
            uint32_t a[4][4], b[8][2];
            #pragma unroll
            for (int mi = 0; mi < 4; ++mi){
                uint32_t addr = aB + (uint32_t)(((a_row + mi * 16) * SROW + k16 + a_colb) * 2);
                ldsm_x4(&a[mi][0], addr);
            }
            #pragma unroll
            for (int nb = 0; nb < 4; ++nb){
                uint32_t addr = bB + (uint32_t)(((b_row + nb * 16) * SROW + k16 + b_colb) * 2);
                uint32_t r[4];
                ldsm_x4(r, addr);
                b[nb * 2][0] = r[0];     b[nb * 2][1] = r[1];
                b[nb * 2 + 1][0] = r[2]; b[nb * 2 + 1][1] = r[3];
            }
            #pragma unroll
            for (int mi = 0; mi < 4; ++mi)
                #pragma unroll
                for (int ni = 0; ni < 8; ++ni)
                    mma16816(acc[mi][ni], a[mi], b[ni]);
        }
    }

    const float* bias = (MODE == 0) ? g_bqkv : bias_ext;
    #pragma unroll
    for (int mi = 0; mi < 4; ++mi){
        #pragma unroll
        for (int ni = 0; ni < 8; ++ni){
            int r = m0 + wm * 64 + mi * 16 + (lane >> 2);
            int c = n0 + wn * 64 + ni * 8 + ((lane & 3) << 1);
            float b0 = bias[c], b1 = bias[c + 1];
            float v0 = acc[mi][ni][0] + b0, v1 = acc[mi][ni][1] + b1;
            float v2 = acc[mi][ni][2] + b0, v3 = acc[mi][ni][3] + b1;
            half* dst = (MODE == 0) ? g_QKV : g_Z16;
            *(half2*)(dst + (size_t)r * NTOT + c)       = __floats2half2_rn(v0, v1);
            *(half2*)(dst + (size_t)(r + 8) * NTOT + c) = __floats2half2_rn(v2, v3);
        }
    }
}

// ---------------------------------------------------------------------------
// Tensor-core per-token attention. 1 warp per token, 8 tokens per block.
// Token SMEM: 48 rows (q 0-15, k 16-31, v 32-47) x 72-half padded stride.
//   E(16x16) = Q·K^T via 8 HMMA; softmax in C-fragments (2 shfls);
//   P fragments = cvt(E frags) in place; O(16x64) = P·V via 8 HMMA
//   with V loaded through ldsm.trans. Output staged in dead Q rows.
//   QKV staged via cp.async (no register round-trip, deeper MLP).
// ---------------------------------------------------------------------------
#define ATOK_ROWS 48
#define ATOK_H (ATOK_ROWS * 72)            // 3456 halfs per token
#define ATTN_DSMEM (8 * ATOK_H * 2)        // 55296 bytes

__global__ void __launch_bounds__(256) attn_mma_kernel(){
    extern __shared__ __align__(16) half sm_a[];
    const int tid = threadIdx.x, lane = tid & 31, w = tid >> 5;
    const size_t tok0 = (size_t)blockIdx.x * 8;

    // cooperative load: 8 tokens x 3072 halfs -> 48 rows x 72-stride each
    {
        const half* src = g_QKV + tok0 * NQKV;
        #pragma unroll
        for (int i = 0; i < 12; ++i){
            int idx = tid + i * 256;          // 0..3071 chunks of 8 halfs
            int tok = idx / 384, j = idx - tok * 384;
            int row = j >> 3, c = j & 7;
            cp_async16(sm_a + tok * ATOK_H + row * 72 + c * 8,
                       src + (size_t)tok * NQKV + j * 8);
        }
        cp_commit();
        cp_wait<0>();
    }
    __syncthreads();

    half* base = sm_a + w * ATOK_H;
    const uint32_t sb = (uint32_t)__cvta_generic_to_shared(base);

    // ---- E = Q K^T  (m16 n16 k64) ----
    float e0[4] = {0,0,0,0}, e1[4] = {0,0,0,0};
    {
        const int q_row  = lane & 15;
        const int q_colb = (lane >> 4) << 3;
        const int k_row  = 16 + (lane & 7) + ((lane >> 4) << 3);
        const int k_colb = ((lane >> 3) & 1) << 3;
        #pragma unroll
        for (int kc = 0; kc < 4; ++kc){
            const int k16 = kc * 16;
            uint32_t qa[4], kr[4];
            ldsm_x4(qa, sb + (uint32_t)((q_row * 72 + k16 + q_colb) * 2));
            ldsm_x4(kr, sb + (uint32_t)((k_row * 72 + k16 + k_colb) * 2));
            mma16816(e0, qa, &kr[0]);     // cols g 0-7
            mma16816(e1, qa, &kr[2]);     // cols g 8-15
        }
    }

    // ---- softmax over g (16 cols), rows r=lane>>2 and r+8 ----
    {
        const float sc = 0.125f;   // 1/sqrt(64)
        e0[0]*=sc; e0[1]*=sc; e0[2]*=sc; e0[3]*=sc;
        e1[0]*=sc; e1[1]*=sc; e1[2]*=sc; e1[3]*=sc;
        float mA = fmaxf(fmaxf(e0[0], e0[1]), fmaxf(e1[0], e1[1]));
        float mB = fmaxf(fmaxf(e0[2], e0[3]), fmaxf(e1[2], e1[3]));
        mA = fmaxf(mA, __shfl_xor_sync(0xffffffffu, mA, 1));
        mA = fmaxf(mA, __shfl_xor_sync(0xffffffffu, mA, 2));
        mB = fmaxf(mB, __shfl_xor_sync(0xffffffffu, mB, 1));
        mB = fmaxf(mB, __shfl_xor_sync(0xffffffffu, mB, 2));
        e0[0] = __expf(e0[0] - mA); e0[1] = __expf(e0[1] - mA);
        e1[0] = __expf(e1[0] - mA); e1[1] = __expf(e1[1] - mA);
        e0[2] = __expf(e0[2] - mB); e0[3] = __expf(e0[3] - mB);
        e1[2] = __expf(e1[2] - mB); e1[3] = __expf(e1[3] - mB);
        float sA = e0[0] + e0[1] + e1[0] + e1[1];
        float sB = e0[2] + e0[3] + e1[2] + e1[3];
        sA += __shfl_xor_sync(0xffffffffu, sA, 1);
        sA += __shfl_xor_sync(0xffffffffu, sA, 2);
        sB += __shfl_xor_sync(0xffffffffu, sB, 1);
        sB += __shfl_xor_sync(0xffffffffu, sB, 2);
        float iA = 1.f / sA, iB = 1.f / sB;
        e0[0]*=iA; e0[1]*=iA; e1[0]*=iA; e1[1]*=iA;
        e0[2]*=iB; e0[3]*=iB; e1[2]*=iB; e1[3]*=iB;
    }

    // ---- P fragments (A operand of O = P V): direct register reuse ----
    uint32_t pa[4];
    pa[0] = h2_to_u32(__floats2half2_rn(e0[0], e0[1]));
    pa[1] = h2_to_u32(__floats2half2_rn(e0[2], e0[3]));
    pa[2] = h2_to_u32(__floats2half2_rn(e1[0], e1[1]));
    pa[3] = h2_to_u32(__floats2half2_rn(e1[2], e1[3]));

    // ---- O = P V  (m16 n64 k16), V via ldsm.trans ----
    float o[8][4];
    #pragma unroll
    for (int nt = 0; nt < 8; ++nt){ o[nt][0]=0; o[nt][1]=0; o[nt][2]=0; o[nt][3]=0; }
    {
        const int v_row = 32 + (lane & 15);
        #pragma unroll
        for (int i = 0; i < 4; ++i){
            const int db = i * 16;
            uint32_t vr[4];
            ldsm_x4_t(vr, sb + (uint32_t)((v_row * 72 + db + ((lane >> 4) << 3)) * 2));
            mma16816(o[i * 2],     pa, &vr[0]);
            mma16816(o[i * 2 + 1], pa, &vr[2]);
        }
    }

    // ---- stage O into dead Q rows (0-15), then coalesced global store ----
    {
        const int r = lane >> 2;
        const int c2 = (lane & 3) << 1;
        #pragma unroll
        for (int nt = 0; nt < 8; ++nt){
            *(half2*)(base + r * 72 + nt * 8 + c2)       = __floats2half2_rn(o[nt][0], o[nt][1]);
            *(half2*)(base + (r + 8) * 72 + nt * 8 + c2) = __floats2half2_rn(o[nt][2], o[nt][3]);
        }
    }
    __syncthreads();

    {
        float4* gout = (float4*)(g_Attn + tok0 * FDIM);
        #pragma unroll
        for (int i = 0; i < 4; ++i){
            int idx = tid + i * 256;          // 0..1023 chunks of 8 halfs
            int tok = idx >> 7, j = idx & 127;
            int row = j >> 3, c = j & 7;
            gout[(size_t)tok * 128 + j] = *(const float4*)(sm_a + tok * ATOK_H + row * 72 + c * 8);
        }
    }
}

// ---------------------------------------------------------------------------
// LayerNorm over F=1024 (reads fp16 Z), one block per row
// ---------------------------------------------------------------------------
__global__ void __launch_bounds__(256) ln_kernel(const float* __restrict__ gamma,
                                                 const float* __restrict__ beta,
                                                 float* __restrict__ out)
{
    const int row = blockIdx.x, t = threadIdx.x, lane = t & 31, wid = t >> 5;
    uint2 raw = ((const uint2*)(g_Z16 + (size_t)row * FDIM))[t];   // 4 halfs
    half2 h01, h23;
    memcpy(&h01, &raw.x, 4);
    memcpy(&h23, &raw.y, 4);
    float2 f01 = __half22float2(h01), f23 = __half22float2(h23);
    float s = f01.x + f01.y + f23.x + f23.y;
    float q = f01.x*f01.x + f01.y*f01.y + f23.x*f23.x + f23.y*f23.y;
    #pragma unroll
    for (int o = 16; o > 0; o >>= 1){
        s += __shfl_xor_sync(0xffffffffu, s, o);
        q += __shfl_xor_sync(0xffffffffu, q, o);
    }
    __shared__ float ws[8], wq[8], mv[2];
    if (lane == 0){ ws[wid] = s; wq[wid] = q; }
    __syncthreads();
    if (t == 0){
        float S = 0.f, Q = 0.f;
        #pragma unroll
        for (int i = 0; i < 8; ++i){ S += ws[i]; Q += wq[i]; }
        float mean = S * (1.f / 1024.f);
        float var  = Q * (1.f / 1024.f) - mean * mean;
        mv[0] = mean; mv[1] = rsqrtf(var + 1e-5f);
    }
    __syncthreads();
    float mean = mv[0], rstd = mv[1];
    float4 g4 = ((const float4*)gamma)[t];
    float4 b4 = ((const float4*)beta)[t];
    float4 r;
    r.x = (f01.x - mean) * rstd * g4.x + b4.x;
    r.y = (f01.y - mean) * rstd * g4.y + b4.y;
    r.z = (f23.x - mean) * rstd * g4.z + b4.z;
    r.w = (f23.y - mean) * rstd * g4.w + b4.w;
    ((float4*)(out + (size_t)row * FDIM))[t] = r;
}

// ---------------------------------------------------------------------------
// Launch
// ---------------------------------------------------------------------------
extern "C" void kernel_launch(void* const* d_in, const int* in_sizes, int n_in,
                              void* d_out, int out_size)
{
    (void)in_sizes; (void)n_in; (void)out_size;
    const float* x     = (const float*)d_in[0];
    const float* Wq    = (const float*)d_in[1];
    const float* bq    = (const float*)d_in[2];
    const float* Wk    = (const float*)d_in[3];
    const float* bk    = (const float*)d_in[4];
    const float* Wv    = (const float*)d_in[5];
    const float* bv    = (const float*)d_in[6];
    const float* Wo    = (const float*)d_in[7];
    const float* bo    = (const float*)d_in[8];
    const float* gamma = (const float*)d_in[9];
    const float* beta  = (const float*)d_in[10];
    float* out = (float*)d_out;

    cudaFuncSetAttribute(gemm_hmma_kernel<0>, cudaFuncAttributeMaxDynamicSharedMemorySize, GEMM_DSMEM);
    cudaFuncSetAttribute(gemm_hmma_kernel<1>, cudaFuncAttributeMaxDynamicSharedMemorySize, GEMM_DSMEM);
    cudaFuncSetAttribute(attn_mma_kernel, cudaFuncAttributeMaxDynamicSharedMemorySize, ATTN_DSMEM);

    convx_kernel<<<4096, 256>>>(x, bq, bk, bv);
    transw_kernel<<<dim3(32, 32, 4), dim3(32, 8)>>>(Wq, Wk, Wv, Wo);
    gemm_hmma_kernel<0><<<dim3(NQKV / BN, TOKENS / BM), 256, GEMM_DSMEM>>>(nullptr);
    attn_mma_kernel<<<TOKENS / 8, 256, ATTN_DSMEM>>>();
    gemm_hmma_kernel<1><<<dim3(FDIM / BN, TOKENS / BM), 256, GEMM_DSMEM>>>(bo);
    ln_kernel<<<TOKENS, 256>>>(gamma, beta, out);
}

// round 9
// speedup vs baseline: 1.2664x; 1.0250x over previous
#include <cuda_runtime.h>
#include <cuda_fp16.h>
#include <cstdint>

// Problem constants
#define TOKENS 32768          // B*S = 16*2048
#define FDIM   1024
#define NQKV   3072
#define NHEAD  16
#define DHEAD  64

// ---------------------------------------------------------------------------
// Scratch (device globals; no allocations allowed)
// ---------------------------------------------------------------------------
__device__ __align__(16) half  g_Wqkv[(size_t)NQKV * FDIM];     // [N=3072, K=1024] transposed
__device__ __align__(16) half  g_Wo16[(size_t)FDIM * FDIM];     // [N=1024, K=1024] transposed
__device__ float               g_bqkv[NQKV];                    // packed biases
__device__ __align__(16) half  g_QKV [(size_t)TOKENS * NQKV];   // q,k,v per token
__device__ __align__(16) half  g_Attn[(size_t)TOKENS * FDIM];   // attention output
__device__ __align__(16) half  g_Z16 [(size_t)TOKENS * FDIM];   // pre-LN output (fp16)

// ---------------------------------------------------------------------------
// PTX helpers
// ---------------------------------------------------------------------------
__device__ __forceinline__ void cp_async16(void* dst, const void* src){
    unsigned s = (unsigned)__cvta_generic_to_shared(dst);
    asm volatile("cp.async.cg.shared.global [%0], [%1], 16;\n" :: "r"(s), "l"(src));
}
__device__ __forceinline__ void cp_commit(){ asm volatile("cp.async.commit_group;\n"); }
template<int N>
__device__ __forceinline__ void cp_wait(){ asm volatile("cp.async.wait_group %0;\n" :: "n"(N)); }

__device__ __forceinline__ void ldsm_x4(uint32_t* r, uint32_t addr){
    asm volatile("ldmatrix.sync.aligned.m8n8.x4.shared.b16 {%0,%1,%2,%3}, [%4];\n"
        : "=r"(r[0]), "=r"(r[1]), "=r"(r[2]), "=r"(r[3]) : "r"(addr));
}
__device__ __forceinline__ void ldsm_x4_t(uint32_t* r, uint32_t addr){
    asm volatile("ldmatrix.sync.aligned.m8n8.x4.trans.shared.b16 {%0,%1,%2,%3}, [%4];\n"
        : "=r"(r[0]), "=r"(r[1]), "=r"(r[2]), "=r"(r[3]) : "r"(addr));
}
__device__ __forceinline__ void mma16816(float* c, const uint32_t* a, const uint32_t* b){
    asm volatile("mma.sync.aligned.m16n8k16.row.col.f32.f16.f16.f32 "
        "{%0,%1,%2,%3}, {%4,%5,%6,%7}, {%8,%9}, {%0,%1,%2,%3};\n"
        : "+f"(c[0]), "+f"(c[1]), "+f"(c[2]), "+f"(c[3])
        : "r"(a[0]), "r"(a[1]), "r"(a[2]), "r"(a[3]), "r"(b[0]), "r"(b[1]));
}
__device__ __forceinline__ uint32_t h2_to_u32(half2 h){
    uint32_t u;
    memcpy(&u, &h, 4);
    return u;
}

// ---------------------------------------------------------------------------
// Pack biases
// ---------------------------------------------------------------------------
__global__ void __launch_bounds__(256) packb_kernel(
    const float* __restrict__ bq, const float* __restrict__ bk, const float* __restrict__ bv)
{
    int i = blockIdx.x * blockDim.x + threadIdx.x;
    if (i < NQKV)
        g_bqkv[i] = (i < 1024) ? bq[i] : (i < 2048) ? bk[i - 1024] : bv[i - 2048];
}

// ---------------------------------------------------------------------------
// Tiled transpose: W[k][n] fp32 -> Wt[n][k] fp16.  z: 0..2 -> Wqkv rows, 3 -> Wo
// ---------------------------------------------------------------------------
__global__ void __launch_bounds__(256) transw_kernel(
    const float* __restrict__ Wq, const float* __restrict__ Wk,
    const float* __restrict__ Wv, const float* __restrict__ Wo)
{
    __shared__ float t[32][33];
    const int z = blockIdx.z;
    const float* src = (z == 0) ? Wq : (z == 1) ? Wk : (z == 2) ? Wv : Wo;
    const int k0 = blockIdx.y * 32, n0 = blockIdx.x * 32;
    const int tx = threadIdx.x, ty = threadIdx.y;   // 32 x 8
    #pragma unroll
    for (int i = 0; i < 4; ++i)
        t[ty + i * 8][tx] = src[(size_t)(k0 + ty + i * 8) * FDIM + n0 + tx];
    __syncthreads();
    half* dst = (z < 3) ? (g_Wqkv + (size_t)z * FDIM * FDIM) : g_Wo16;
    #pragma unroll
    for (int i = 0; i < 4; ++i)
        dst[(size_t)(n0 + ty + i * 8) * FDIM + k0 + tx] = __float2half_rn(t[tx][ty + i * 8]);
}

// ---------------------------------------------------------------------------
// HMMA GEMM: C[M,NTOT] = A[M,1024] * B[NTOT,1024]^T + bias
//   CTA tile 128x256, 8 warps (2x4), warp tile 64x64, BK=64, 4-stage ring.
// MODE 0: A = x (fp32, converted inline!), B=g_Wqkv, C=g_QKV, bias=g_bqkv
//         A path: early LDG.128 (pre-barrier) -> cvt+STS (post-MMA), so the
//         global latency hides under the HMMA shadow of the current stage.
// MODE 1: A = g_Attn (fp16, cp.async), B=g_Wo16, C=g_Z16, bias=bias_ext
// ---------------------------------------------------------------------------
#define BM 128
#define BN 256
#define BK 64
#define SROW 72
#define A_ST_BYTES (BM * SROW * 2)
#define B_ST_BYTES (BN * SROW * 2)
#define STAGE_BYTES (A_ST_BYTES + B_ST_BYTES)
#define NSTAGES 4
#define NKBLK (FDIM / BK)
#define GEMM_DSMEM (NSTAGES * STAGE_BYTES)

template<int MODE>
__global__ void __launch_bounds__(256, 1) gemm_hmma_kernel(
    const float* __restrict__ xf, const float* __restrict__ bias_ext)
{
    constexpr int NTOT = (MODE == 0) ? NQKV : FDIM;
    const half* __restrict__ Bw = (MODE == 0) ? g_Wqkv : g_Wo16;

    extern __shared__ __align__(16) half sm[];

    const int tid  = threadIdx.x;
    const int lane = tid & 31;
    const int wid  = tid >> 5;
    const int wm   = wid & 1;
    const int wn   = wid >> 1;
    const int m0 = blockIdx.y * BM;
    const int n0 = blockIdx.x * BN;

    const float* Xbase = (MODE == 0) ? (xf + (size_t)m0 * FDIM) : nullptr;
    const half*  Abase = (MODE == 0) ? nullptr : (g_Attn + (size_t)m0 * FDIM);
    const half*  Bbase = Bw + (size_t)n0 * FDIM;

    float acc[4][8][4];
    #pragma unroll
    for (int mi = 0; mi < 4; ++mi)
        #pragma unroll
        for (int ni = 0; ni < 8; ++ni)
            #pragma unroll
            for (int t = 0; t < 4; ++t) acc[mi][ni][t] = 0.f;

    // B tile: 8 cp.async per thread + commit (one group per stage)
    auto loadB = [&](int s){
        const int buf = s & (NSTAGES - 1);
        half* bs = sm + (size_t)buf * (STAGE_BYTES / 2) + (A_ST_BYTES / 2);
        const half* Bsrc = Bbase + s * BK;
        #pragma unroll
        for (int i = 0; i < 8; ++i){
            int idx = tid + i * 256;
            int r = idx >> 3, c = idx & 7;
            cp_async16(bs + r * SROW + c * 8, Bsrc + (size_t)r * FDIM + c * 8);
        }
        cp_commit();
    };
    // MODE 1: A tile via cp.async (same group as B; call before loadB)
    auto loadA_async = [&](int s){
        const int buf = s & (NSTAGES - 1);
        half* as = sm + (size_t)buf * (STAGE_BYTES / 2);
        const half* Asrc = Abase + s * BK;
        #pragma unroll
        for (int i = 0; i < 4; ++i){
            int idx = tid + i * 256;
            int r = idx >> 3, c = idx & 7;
            cp_async16(as + r * SROW + c * 8, Asrc + (size_t)r * FDIM + c * 8);
        }
    };
    // MODE 0: A tile fp32 LDG into registers
    auto ldgA = [&](int s, float4* ar){
        const float* Asrc = Xbase + s * BK;
        #pragma unroll
        for (int i = 0; i < 4; ++i){
            int idx = tid + i * 256;
            int r = idx >> 3, c = idx & 7;
            const float4* p = (const float4*)(Asrc + (size_t)r * FDIM + c * 8);
            ar[2 * i]     = p[0];
            ar[2 * i + 1] = p[1];
        }
    };
    // MODE 0: convert + STS into the stage buffer
    auto stsA = [&](int s, const float4* ar){
        const int buf = s & (NSTAGES - 1);
        half* as = sm + (size_t)buf * (STAGE_BYTES / 2);
        #pragma unroll
        for (int i = 0; i < 4; ++i){
            int idx = tid + i * 256;
            int r = idx >> 3, c = idx & 7;
            float4 a0 = ar[2 * i], a1 = ar[2 * i + 1];
            uint4 packed;
            packed.x = h2_to_u32(__floats2half2_rn(a0.x, a0.y));
            packed.y = h2_to_u32(__floats2half2_rn(a0.z, a0.w));
            packed.z = h2_to_u32(__floats2half2_rn(a1.x, a1.y));
            packed.w = h2_to_u32(__floats2half2_rn(a1.z, a1.w));
            *(uint4*)(as + r * SROW + c * 8) = packed;
        }
    };

    // prologue: stages 0..2
    #pragma unroll
    for (int s = 0; s < 3; ++s){
        if constexpr (MODE == 0){
            float4 ar[8];
            ldgA(s, ar);
            stsA(s, ar);
        } else {
            loadA_async(s);
        }
        loadB(s);
    }

    const int a_row = wm * 64 + (lane & 15);
    const int a_colb = (lane >> 4) << 3;
    const int b_row = wn * 64 + (lane & 7) + ((lane >> 4) << 3);
    const int b_colb = ((lane >> 3) & 1) << 3;

    for (int s = 0; s < NKBLK; ++s){
        const bool pre = (s + 3 < NKBLK);
        float4 ar[8];
        if constexpr (MODE == 0){
            if (pre) ldgA(s + 3, ar);       // LDG early: latency hides under MMA
        }

        const int rem = (NKBLK - 1) - s;
        if (rem >= 2)      cp_wait<2>();
        else if (rem == 1) cp_wait<1>();
        else               cp_wait<0>();
        __syncthreads();

        if (pre){
            if constexpr (MODE == 1) loadA_async(s + 3);
            loadB(s + 3);
        }

        const int buf = s & (NSTAGES - 1);
        const half* as = sm + (size_t)buf * (STAGE_BYTES / 2);
        const half* bs = as + (A_ST_BYTES / 2);
        const uint32_t aB = (uint32_t)__cvta_generic_to_shared(as);
        const uint32_t bB = (uint32_t)__cvta_generic_to_shared(bs);

        #pragma unroll
        for (int kk = 0; kk < 4; ++kk){
            const int k16 = kk * 16;
            uint32_t a[4][4], b[8][2];
            #pragma unroll
            for (int mi = 0; mi < 4; ++mi){
                uint32_t addr = aB + (uint32_t)(((a_row + mi * 16) * SROW + k16 + a_colb) * 2);
                ldsm_x4(&a[mi][0], addr);
            }
            #pragma unroll
            for (int nb = 0; nb < 4; ++nb){
                uint32_t addr = bB + (uint32_t)(((b_row + nb * 16) * SROW + k16 + b_colb) * 2);
                uint32_t r[4];
                ldsm_x4(r, addr);
                b[nb * 2][0] = r[0];     b[nb * 2][1] = r[1];
                b[nb * 2 + 1][0] = r[2]; b[nb * 2 + 1][1] = r[3];
            }
            #pragma unroll
            for (int mi = 0; mi < 4; ++mi)
                #pragma unroll
                for (int ni = 0; ni < 8; ++ni)
                    mma16816(acc[mi][ni], a[mi], b[ni]);
        }

        if constexpr (MODE == 0){
            if (pre) stsA(s + 3, ar);       // buffer (s+3)&3 freed by this stage's barrier
        }
    }

    const float* bias = (MODE == 0) ? g_bqkv : bias_ext;
    #pragma unroll
    for (int mi = 0; mi < 4; ++mi){
        #pragma unroll
        for (int ni = 0; ni < 8; ++ni){
            int r = m0 + wm * 64 + mi * 16 + (lane >> 2);
            int c = n0 + wn * 64 + ni * 8 + ((lane & 3) << 1);
            float b0 = bias[c], b1 = bias[c + 1];
            float v0 = acc[mi][ni][0] + b0, v1 = acc[mi][ni][1] + b1;
            float v2 = acc[mi][ni][2] + b0, v3 = acc[mi][ni][3] + b1;
            half* dst = (MODE == 0) ? g_QKV : g_Z16;
            *(half2*)(dst + (size_t)r * NTOT + c)       = __floats2half2_rn(v0, v1);
            *(half2*)(dst + (size_t)(r + 8) * NTOT + c) = __floats2half2_rn(v2, v3);
        }
    }
}

// ---------------------------------------------------------------------------
// Tensor-core per-token attention. 1 warp per token, 8 tokens per block.
// Token SMEM: 48 rows (q 0-15, k 16-31, v 32-47) x 72-half padded stride.
// ---------------------------------------------------------------------------
#define ATOK_ROWS 48
#define ATOK_H (ATOK_ROWS * 72)            // 3456 halfs per token
#define ATTN_DSMEM (8 * ATOK_H * 2)        // 55296 bytes

__global__ void __launch_bounds__(256) attn_mma_kernel(){
    extern __shared__ __align__(16) half sm_a[];
    const int tid = threadIdx.x, lane = tid & 31, w = tid >> 5;
    const size_t tok0 = (size_t)blockIdx.x * 8;

    // cooperative load: 8 tokens x 3072 halfs -> 48 rows x 72-stride each
    {
        const half* src = g_QKV + tok0 * NQKV;
        #pragma unroll
        for (int i = 0; i < 12; ++i){
            int idx = tid + i * 256;          // 0..3071 chunks of 8 halfs
            int tok = idx / 384, j = idx - tok * 384;
            int row = j >> 3, c = j & 7;
            cp_async16(sm_a + tok * ATOK_H + row * 72 + c * 8,
                       src + (size_t)tok * NQKV + j * 8);
        }
        cp_commit();
        cp_wait<0>();
    }
    __syncthreads();

    half* base = sm_a + w * ATOK_H;
    const uint32_t sb = (uint32_t)__cvta_generic_to_shared(base);

    // ---- E = Q K^T  (m16 n16 k64) ----
    float e0[4] = {0,0,0,0}, e1[4] = {0,0,0,0};
    {
        const int q_row  = lane & 15;
        const int q_colb = (lane >> 4) << 3;
        const int k_row  = 16 + (lane & 7) + ((lane >> 4) << 3);
        const int k_colb = ((lane >> 3) & 1) << 3;
        #pragma unroll
        for (int kc = 0; kc < 4; ++kc){
            const int k16 = kc * 16;
            uint32_t qa[4], kr[4];
            ldsm_x4(qa, sb + (uint32_t)((q_row * 72 + k16 + q_colb) * 2));
            ldsm_x4(kr, sb + (uint32_t)((k_row * 72 + k16 + k_colb) * 2));
            mma16816(e0, qa, &kr[0]);     // cols g 0-7
            mma16816(e1, qa, &kr[2]);     // cols g 8-15
        }
    }

    // ---- softmax over g (16 cols), rows r=lane>>2 and r+8 ----
    {
        const float sc = 0.125f;   // 1/sqrt(64)
        e0[0]*=sc; e0[1]*=sc; e0[2]*=sc; e0[3]*=sc;
        e1[0]*=sc; e1[1]*=sc; e1[2]*=sc; e1[3]*=sc;
        float mA = fmaxf(fmaxf(e0[0], e0[1]), fmaxf(e1[0], e1[1]));
        float mB = fmaxf(fmaxf(e0[2], e0[3]), fmaxf(e1[2], e1[3]));
        mA = fmaxf(mA, __shfl_xor_sync(0xffffffffu, mA, 1));
        mA = fmaxf(mA, __shfl_xor_sync(0xffffffffu, mA, 2));
        mB = fmaxf(mB, __shfl_xor_sync(0xffffffffu, mB, 1));
        mB = fmaxf(mB, __shfl_xor_sync(0xffffffffu, mB, 2));
        e0[0] = __expf(e0[0] - mA); e0[1] = __expf(e0[1] - mA);
        e1[0] = __expf(e1[0] - mA); e1[1] = __expf(e1[1] - mA);
        e0[2] = __expf(e0[2] - mB); e0[3] = __expf(e0[3] - mB);
        e1[2] = __expf(e1[2] - mB); e1[3] = __expf(e1[3] - mB);
        float sA = e0[0] + e0[1] + e1[0] + e1[1];
        float sB = e0[2] + e0[3] + e1[2] + e1[3];
        sA += __shfl_xor_sync(0xffffffffu, sA, 1);
        sA += __shfl_xor_sync(0xffffffffu, sA, 2);
        sB += __shfl_xor_sync(0xffffffffu, sB, 1);
        sB += __shfl_xor_sync(0xffffffffu, sB, 2);
        float iA = 1.f / sA, iB = 1.f / sB;
        e0[0]*=iA; e0[1]*=iA; e1[0]*=iA; e1[1]*=iA;
        e0[2]*=iB; e0[3]*=iB; e1[2]*=iB; e1[3]*=iB;
    }

    // ---- P fragments (A operand of O = P V): direct register reuse ----
    uint32_t pa[4];
    pa[0] = h2_to_u32(__floats2half2_rn(e0[0], e0[1]));
    pa[1] = h2_to_u32(__floats2half2_rn(e0[2], e0[3]));
    pa[2] = h2_to_u32(__floats2half2_rn(e1[0], e1[1]));
    pa[3] = h2_to_u32(__floats2half2_rn(e1[2], e1[3]));

    // ---- O = P V  (m16 n64 k16), V via ldsm.trans ----
    float o[8][4];
    #pragma unroll
    for (int nt = 0; nt < 8; ++nt){ o[nt][0]=0; o[nt][1]=0; o[nt][2]=0; o[nt][3]=0; }
    {
        const int v_row = 32 + (lane & 15);
        #pragma unroll
        for (int i = 0; i < 4; ++i){
            const int db = i * 16;
            uint32_t vr[4];
            ldsm_x4_t(vr, sb + (uint32_t)((v_row * 72 + db + ((lane >> 4) << 3)) * 2));
            mma16816(o[i * 2],     pa, &vr[0]);
            mma16816(o[i * 2 + 1], pa, &vr[2]);
        }
    }

    // ---- stage O into dead Q rows (0-15), then coalesced global store ----
    {
        const int r = lane >> 2;
        const int c2 = (lane & 3) << 1;
        #pragma unroll
        for (int nt = 0; nt < 8; ++nt){
            *(half2*)(base + r * 72 + nt * 8 + c2)       = __floats2half2_rn(o[nt][0], o[nt][1]);
            *(half2*)(base + (r + 8) * 72 + nt * 8 + c2) = __floats2half2_rn(o[nt][2], o[nt][3]);
        }
    }
    __syncthreads();

    {
        float4* gout = (float4*)(g_Attn + tok0 * FDIM);
        #pragma unroll
        for (int i = 0; i < 4; ++i){
            int idx = tid + i * 256;          // 0..1023 chunks of 8 halfs
            int tok = idx >> 7, j = idx & 127;
            int row = j >> 3, c = j & 7;
            gout[(size_t)tok * 128 + j] = *(const float4*)(sm_a + tok * ATOK_H + row * 72 + c * 8);
        }
    }
}

// ---------------------------------------------------------------------------
// LayerNorm over F=1024 (reads fp16 Z), one block per row
// ---------------------------------------------------------------------------
__global__ void __launch_bounds__(256) ln_kernel(const float* __restrict__ gamma,
                                                 const float* __restrict__ beta,
                                                 float* __restrict__ out)
{
    const int row = blockIdx.x, t = threadIdx.x, lane = t & 31, wid = t >> 5;
    uint2 raw = ((const uint2*)(g_Z16 + (size_t)row * FDIM))[t];   // 4 halfs
    half2 h01, h23;
    memcpy(&h01, &raw.x, 4);
    memcpy(&h23, &raw.y, 4);
    float2 f01 = __half22float2(h01), f23 = __half22float2(h23);
    float s = f01.x + f01.y + f23.x + f23.y;
    float q = f01.x*f01.x + f01.y*f01.y + f23.x*f23.x + f23.y*f23.y;
    #pragma unroll
    for (int o = 16; o > 0; o >>= 1){
        s += __shfl_xor_sync(0xffffffffu, s, o);
        q += __shfl_xor_sync(0xffffffffu, q, o);
    }
    __shared__ float ws[8], wq[8], mv[2];
    if (lane == 0){ ws[wid] = s; wq[wid] = q; }
    __syncthreads();
    if (t == 0){
        float S = 0.f, Q = 0.f;
        #pragma unroll
        for (int i = 0; i < 8; ++i){ S += ws[i]; Q += wq[i]; }
        float mean = S * (1.f / 1024.f);
        float var  = Q * (1.f / 1024.f) - mean * mean;
        mv[0] = mean; mv[1] = rsqrtf(var + 1e-5f);
    }
    __syncthreads();
    float mean = mv[0], rstd = mv[1];
    float4 g4 = ((const float4*)gamma)[t];
    float4 b4 = ((const float4*)beta)[t];
    float4 r;
    r.x = (f01.x - mean) * rstd * g4.x + b4.x;
    r.y = (f01.y - mean) * rstd * g4.y + b4.y;
    r.z = (f23.x - mean) * rstd * g4.z + b4.z;
    r.w = (f23.y - mean) * rstd * g4.w + b4.w;
    ((float4*)(out + (size_t)row * FDIM))[t] = r;
}

// ---------------------------------------------------------------------------
// Launch
// ---------------------------------------------------------------------------
extern "C" void kernel_launch(void* const* d_in, const int* in_sizes, int n_in,
                              void* d_out, int out_size)
{
    (void)in_sizes; (void)n_in; (void)out_size;
    const float* x     = (const float*)d_in[0];
    const float* Wq    = (const float*)d_in[1];
    const float* bq    = (const float*)d_in[2];
    const float* Wk    = (const float*)d_in[3];
    const float* bk    = (const float*)d_in[4];
    const float* Wv    = (const float*)d_in[5];
    const float* bv    = (const float*)d_in[6];
    const float* Wo    = (const float*)d_in[7];
    const float* bo    = (const float*)d_in[8];
    const float* gamma = (const float*)d_in[9];
    const float* beta  = (const float*)d_in[10];
    float* out = (float*)d_out;

    cudaFuncSetAttribute(gemm_hmma_kernel<0>, cudaFuncAttributeMaxDynamicSharedMemorySize, GEMM_DSMEM);
    cudaFuncSetAttribute(gemm_hmma_kernel<1>, cudaFuncAttributeMaxDynamicSharedMemorySize, GEMM_DSMEM);
    cudaFuncSetAttribute(attn_mma_kernel, cudaFuncAttributeMaxDynamicSharedMemorySize, ATTN_DSMEM);

    packb_kernel<<<12, 256>>>(bq, bk, bv);
    transw_kernel<<<dim3(32, 32, 4), dim3(32, 8)>>>(Wq, Wk, Wv, Wo);
    gemm_hmma_kernel<0><<<dim3(NQKV / BN, TOKENS / BM), 256, GEMM_DSMEM>>>(x, nullptr);
    attn_mma_kernel<<<TOKENS / 8, 256, ATTN_DSMEM>>>();
    gemm_hmma_kernel<1><<<dim3(FDIM / BN, TOKENS / BM), 256, GEMM_DSMEM>>>(nullptr, bo);
    ln_kernel<<<TOKENS, 256>>>(gamma, beta, out);
}